// round 7
// baseline (speedup 1.0000x reference)
#include <cuda_runtime.h>
#include <math.h>

#define NP 3136
#define Bb 2
#define CN 802816L
#define C2N 1605632L
#define TOT 1605632L

static __device__ float g_sq  [TOT];
static __device__ float g_skv [Bb*C2N];
static __device__ float g_tq  [TOT];
static __device__ float g_tkv [Bb*C2N];
static __device__ float g_vloc[TOT];
static __device__ float g_f1r [TOT];
static __device__ float g_f1i [TOT];
static __device__ float g_f2r [TOT];
static __device__ float g_f2i [TOT];
static __device__ float g_f3r [TOT];
static __device__ float g_f3i [TOT];
static __device__ float g_spre[TOT];
static __device__ float g_xat [TOT];
static __device__ float g_fusb[Bb*C2N];
static __device__ float g_hbuf[TOT];
static __device__ float g_gate[Bb*NP];

// Y[b][o][n] = sum_i W[o][i]*X[b][i][n] (+bias[o]); N=3136. grid(49, O/64, B), block 256
__global__ void gemm_k(const float* __restrict__ W, const float* __restrict__ X,
                       float* __restrict__ Y, const float* __restrict__ bias,
                       int I, long xB, long yB)
{
    __shared__ float Ws[64][17];
    __shared__ float Xs[16][64];
    int tid = threadIdx.x, tx = tid & 15, ty = tid >> 4;
    int nb = blockIdx.x * 64, ob = blockIdx.y * 64;
    const float* Xb = X + (long)blockIdx.z * xB;
    float*       Yb = Y + (long)blockIdx.z * yB;
    float acc[4][4];
#pragma unroll
    for (int i = 0; i < 4; i++)
#pragma unroll
        for (int j = 0; j < 4; j++) acc[i][j] = 0.f;
    for (int kt = 0; kt < I; kt += 16) {
#pragma unroll
        for (int l = 0; l < 4; l++) {
            int idx = l * 256 + tid;
            Ws[idx >> 4][idx & 15] = W[(long)(ob + (idx >> 4)) * I + kt + (idx & 15)];
            Xs[idx >> 6][idx & 63] = Xb[(long)(kt + (idx >> 6)) * NP + nb + (idx & 63)];
        }
        __syncthreads();
#pragma unroll
        for (int kk = 0; kk < 16; kk++) {
            float4 b4 = *(const float4*)&Xs[kk][tx * 4];
            float bv[4] = {b4.x, b4.y, b4.z, b4.w};
            float av[4] = {Ws[ty*4+0][kk], Ws[ty*4+1][kk], Ws[ty*4+2][kk], Ws[ty*4+3][kk]};
#pragma unroll
            for (int i = 0; i < 4; i++)
#pragma unroll
                for (int j = 0; j < 4; j++)
                    acc[i][j] = fmaf(av[i], bv[j], acc[i][j]);
        }
        __syncthreads();
    }
#pragma unroll
    for (int i = 0; i < 4; i++) {
        int o = ob + ty * 4 + i;
        float bs = bias ? bias[o] : 0.f;
#pragma unroll
        for (int j = 0; j < 4; j++)
            Yb[(long)o * NP + nb + tx * 4 + j] = acc[i][j] + bs;
    }
}

// depthwise 3x3 'SAME' on v half of spectral kv. grid(256,2), block 256
__global__ void dwconv_k(const float* __restrict__ KV, const float* __restrict__ w,
                         const float* __restrict__ bias, float* __restrict__ out)
{
    int c = blockIdx.x, b = blockIdx.y;
    __shared__ float vs[NP];
    const float* vp = KV + ((long)b * 512 + 256 + c) * NP;
    for (int i = threadIdx.x; i < NP; i += 256) vs[i] = vp[i];
    __syncthreads();
    float wr[9];
#pragma unroll
    for (int i = 0; i < 9; i++) wr[i] = w[c * 9 + i];
    float bsv = bias[c];
    long ob = ((long)b * 256 + c) * NP;
    for (int o = threadIdx.x; o < NP; o += 256) {
        int y = o / 56, x = o % 56;
        float acc = bsv;
#pragma unroll
        for (int dy = -1; dy <= 1; dy++) {
            int yy = y + dy;
            if ((unsigned)yy >= 56u) continue;
#pragma unroll
            for (int dx = -1; dx <= 1; dx++) {
                int xx = x + dx;
                if ((unsigned)xx >= 56u) continue;
                acc += wr[(dy + 1) * 3 + dx + 1] * vs[yy * 56 + xx];
            }
        }
        out[ob + o] = acc;
    }
}

__device__ __forceinline__ void load_tw(float* tc, float* ts)
{
    int t = threadIdx.x;
    if (t < 56) {
        double a = 2.0 * (double)t / 56.0;
        tc[t] = (float)cospi(a);
        ts[t] = (float)sinpi(a);
    }
}

// along-W r2c: out[r][k] = sum_n in[r][n] e^{-i*2pi*k*n/56}. grid(256,B), block 256
__global__ void dftW_r2c_k(const float* __restrict__ in, long inB,
                           float* __restrict__ ore, float* __restrict__ oim)
{
    __shared__ float xs[NP];
    __shared__ float tc[56], ts[56];
    load_tw(tc, ts);
    const float* ib = in + (long)blockIdx.y * inB + (long)blockIdx.x * NP;
    for (int i = threadIdx.x; i < NP; i += 256) xs[i] = ib[i];
    __syncthreads();
    long ob = ((long)blockIdx.y * 256 + blockIdx.x) * NP;
    for (int o = threadIdx.x; o < NP; o += 256) {
        int r = o / 56, k = o % 56;
        const float* xr = xs + r * 56;
        float ac = 0.f, as = 0.f;
        int m = 0;
#pragma unroll 14
        for (int n = 0; n < 56; n++) {
            float v = xr[n];
            ac = fmaf(v, tc[m], ac);
            as = fmaf(v, ts[m], as);
            m += k; if (m >= 56) m -= 56;
        }
        ore[ob + o] = ac;
        oim[ob + o] = -as;
    }
}

// along-H c2c, forward (e^{-i...})
__global__ void dftH_c2c_k(const float* __restrict__ ir, const float* __restrict__ ii,
                           float* __restrict__ ore, float* __restrict__ oim)
{
    __shared__ float xr[NP], xi[NP];
    __shared__ float tc[56], ts[56];
    load_tw(tc, ts);
    long base = ((long)blockIdx.y * 256 + blockIdx.x) * NP;
    for (int i = threadIdx.x; i < NP; i += 256) { xr[i] = ir[base + i]; xi[i] = ii[base + i]; }
    __syncthreads();
    for (int o = threadIdx.x; o < NP; o += 256) {
        int k = o / 56, col = o % 56;
        float pcr = 0.f, psi = 0.f, pci = 0.f, psr = 0.f;
        int m = 0;
#pragma unroll 14
        for (int r = 0; r < 56; r++) {
            float c = tc[m], s = ts[m];
            float vr = xr[r * 56 + col], vi = xi[r * 56 + col];
            pcr = fmaf(c, vr, pcr); psi = fmaf(s, vi, psi);
            pci = fmaf(c, vi, pci); psr = fmaf(s, vr, psr);
            m += k; if (m >= 56) m -= 56;
        }
        ore[base + o] = pcr + psi;
        oim[base + o] = pci - psr;
    }
}

// along-W c2c, inverse (e^{+i...}), unnormalized
__global__ void dftW_c2c_inv_k(const float* __restrict__ ir, const float* __restrict__ ii,
                               float* __restrict__ ore, float* __restrict__ oim)
{
    __shared__ float xr[NP], xi[NP];
    __shared__ float tc[56], ts[56];
    load_tw(tc, ts);
    long base = ((long)blockIdx.y * 256 + blockIdx.x) * NP;
    for (int i = threadIdx.x; i < NP; i += 256) { xr[i] = ir[base + i]; xi[i] = ii[base + i]; }
    __syncthreads();
    for (int o = threadIdx.x; o < NP; o += 256) {
        int r = o / 56, xx = o % 56;
        const float* xrr = xr + r * 56;
        const float* xii = xi + r * 56;
        float pcr = 0.f, psi = 0.f, pci = 0.f, psr = 0.f;
        int m = 0;
#pragma unroll 14
        for (int kk = 0; kk < 56; kk++) {
            float c = tc[m], s = ts[m];
            float vr = xrr[kk], vi = xii[kk];
            pcr = fmaf(c, vr, pcr); psi = fmaf(s, vi, psi);
            pci = fmaf(c, vi, pci); psr = fmaf(s, vr, psr);
            m += xx; if (m >= 56) m -= 56;
        }
        ore[base + o] = pcr - psi;
        oim[base + o] = pci + psr;
    }
}

// inverse-H (real part, e^{+i...}) * scale * v + v_local
__global__ void spec_final_k(const float* __restrict__ ir, const float* __restrict__ ii,
                             const float* __restrict__ KV, const float* __restrict__ vloc,
                             float* __restrict__ out)
{
    __shared__ float xr[NP], xi[NP];
    __shared__ float tc[56], ts[56];
    load_tw(tc, ts);
    int c = blockIdx.x, b = blockIdx.y;
    long base = ((long)b * 256 + c) * NP;
    for (int i = threadIdx.x; i < NP; i += 256) { xr[i] = ir[base + i]; xi[i] = ii[base + i]; }
    __syncthreads();
    const float* vp = KV + ((long)b * 512 + 256 + c) * NP;
    const float sc = 1.0f / 175616.0f;   // 1/N^{3/2}: ortho*ortho circular conv
    for (int o = threadIdx.x; o < NP; o += 256) {
        int y = o / 56, col = o % 56;
        float p1 = 0.f, p2 = 0.f;
        int m = 0;
#pragma unroll 14
        for (int r = 0; r < 56; r++) {
            p1 = fmaf(tc[m], xr[r * 56 + col], p1);
            p2 = fmaf(ts[m], xi[r * 56 + col], p2);
            m += y; if (m >= 56) m -= 56;
        }
        out[base + o] = (sc * (p1 - p2)) * vp[o] + vloc[base + o];
    }
}

// inverse-H (real part), scale 1/3136, accumulate into x_attn
__global__ void token_final_k(const float* __restrict__ ir, const float* __restrict__ ii,
                              float* __restrict__ out)
{
    __shared__ float xr[NP], xi[NP];
    __shared__ float tc[56], ts[56];
    load_tw(tc, ts);
    long base = ((long)blockIdx.y * 256 + blockIdx.x) * NP;
    for (int i = threadIdx.x; i < NP; i += 256) { xr[i] = ir[base + i]; xi[i] = ii[base + i]; }
    __syncthreads();
    const float sc = 1.0f / 3136.0f;
    for (int o = threadIdx.x; o < NP; o += 256) {
        int y = o / 56, col = o % 56;
        float p1 = 0.f, p2 = 0.f;
        int m = 0;
#pragma unroll 14
        for (int r = 0; r < 56; r++) {
            p1 = fmaf(tc[m], xr[r * 56 + col], p1);
            p2 = fmaf(ts[m], xi[r * 56 + col], p2);
            m += y; if (m >= 56) m -= 56;
        }
        out[base + o] += sc * (p1 - p2);
    }
}

__global__ void cmul_k(float* __restrict__ ar_, float* __restrict__ ai_,
                       const float* __restrict__ br_, const float* __restrict__ bi_, long n)
{
    long i = (long)blockIdx.x * blockDim.x + threadIdx.x;
    if (i < n) {
        float ar = ar_[i], ai = ai_[i], br = br_[i], bi = bi_[i];
        ar_[i] = ar * br - ai * bi;
        ai_[i] = ar * bi + ai * br;
    }
}

// multiply full spectrum by Hermitian-extended complex weight (interior-kx mirror only)
__global__ void twmul_k(float* __restrict__ fr, float* __restrict__ fi,
                        const float* __restrict__ cw)
{
    int c = blockIdx.x, b = blockIdx.y;
    long base = ((long)b * 256 + c) * NP;
    for (int o = threadIdx.x; o < NP; o += 256) {
        int ky = o / 56, kx = o % 56;
        float wr, wi;
        if (kx <= 28) {
            long wb = (((long)c * 56 + ky) * 29 + kx) * 2;
            wr = cw[wb]; wi = cw[wb + 1];
        } else {
            int ky2 = (56 - ky) % 56, kx2 = 56 - kx;
            long wb = (((long)c * 56 + ky2) * 29 + kx2) * 2;
            wr = cw[wb]; wi = -cw[wb + 1];
        }
        float vr = fr[base + o], vi = fi[base + o];
        fr[base + o] = vr * wr - vi * wi;
        fi[base + o] = vr * wi + vi * wr;
    }
}

// flash attention: grid(25,8,2), block 128; 1 query/thread, 32-key smem tiles
__global__ void flash_k(const float* __restrict__ Q, const float* __restrict__ KV,
                        float* __restrict__ O)
{
    const float SCALE = 0.17677669529663687f;
    int b = blockIdx.z, h = blockIdx.y, t = threadIdx.x;
    int qi = blockIdx.x * 128 + t;
    bool act = qi < NP;
    const float* Qb = Q + ((long)b * 256 + h * 32) * NP;
    const float* Kb = KV + ((long)b * 512 + h * 32) * NP;
    const float* Vb = KV + ((long)b * 512 + 256 + h * 32) * NP;
    __shared__ float Ks[32][32];
    __shared__ float Vs[32][32];
    float qv[32];
#pragma unroll
    for (int d = 0; d < 32; d++) qv[d] = act ? Qb[(long)d * NP + qi] * SCALE : 0.f;
    float m = -1e30f, l = 0.f, o[32];
#pragma unroll
    for (int d = 0; d < 32; d++) o[d] = 0.f;
    for (int kt = 0; kt < 98; kt++) {
        int kb = kt * 32;
        __syncthreads();
#pragma unroll
        for (int i = t; i < 1024; i += 128) {
            int d = i >> 5, j = i & 31;
            Ks[j][d] = Kb[(long)d * NP + kb + j];
            Vs[j][d] = Vb[(long)d * NP + kb + j];
        }
        __syncthreads();
        float s[32], tm = -1e30f;
#pragma unroll
        for (int j = 0; j < 32; j++) {
            const float4* kp = (const float4*)Ks[j];
            float acc = 0.f;
#pragma unroll
            for (int dd = 0; dd < 8; dd++) {
                float4 kk = kp[dd];
                acc = fmaf(qv[dd*4+0], kk.x, acc);
                acc = fmaf(qv[dd*4+1], kk.y, acc);
                acc = fmaf(qv[dd*4+2], kk.z, acc);
                acc = fmaf(qv[dd*4+3], kk.w, acc);
            }
            s[j] = acc;
            tm = fmaxf(tm, acc);
        }
        float mn = fmaxf(m, tm);
        float corr = __expf(m - mn);
        l *= corr;
#pragma unroll
        for (int d = 0; d < 32; d++) o[d] *= corr;
#pragma unroll
        for (int j = 0; j < 32; j++) {
            float p = __expf(s[j] - mn);
            l += p;
            const float4* vp = (const float4*)Vs[j];
#pragma unroll
            for (int dd = 0; dd < 8; dd++) {
                float4 vv = vp[dd];
                o[dd*4+0] = fmaf(p, vv.x, o[dd*4+0]);
                o[dd*4+1] = fmaf(p, vv.y, o[dd*4+1]);
                o[dd*4+2] = fmaf(p, vv.z, o[dd*4+2]);
                o[dd*4+3] = fmaf(p, vv.w, o[dd*4+3]);
            }
        }
        m = mn;
    }
    if (act) {
        float inv = 1.f / l;
        float* Ob = O + ((long)b * 256 + h * 32) * NP;
#pragma unroll
        for (int d = 0; d < 32; d++) Ob[(long)d * NP + qi] = o[d] * inv;
    }
}

// gate[b][n] = sigmoid(sum_c w2[c]*relu(h*inv*gam+bet) + b2)
__global__ void gate_k(const float* __restrict__ hraw, const float* __restrict__ gam,
                       const float* __restrict__ bet, const float* __restrict__ w2,
                       const float* __restrict__ b2p, float* __restrict__ gate)
{
    int b = blockIdx.y;
    int n = blockIdx.x * 128 + threadIdx.x;
    if (n >= NP) return;
    const float inv = rsqrtf(1.f + 1e-5f);
    const float* hb = hraw + (long)b * CN + n;
    float g = b2p[0];
#pragma unroll 8
    for (int c = 0; c < 256; c++) {
        float hv = hb[(long)c * NP] * inv * gam[c] + bet[c];
        g = fmaf(w2[c], fmaxf(hv, 0.f), g);
    }
    gate[(long)b * NP + n] = 1.f / (1.f + __expf(-g));
}

__global__ void blend_k(const float* __restrict__ fuse, const float* __restrict__ gate,
                        float* __restrict__ out)
{
    long i = (long)blockIdx.x * blockDim.x + threadIdx.x;
    if (i >= TOT) return;
    long b = i / CN;
    long n = i % NP;
    float g = gate[b * NP + n];
    long fidx = i + b * CN;
    float osv = fuse[fidx];
    float otv = fuse[fidx + CN];
    out[i] = g * osv + (1.f - g) * otv;
}

extern "C" void kernel_launch(void* const* d_in, const int* in_sizes, int n_in,
                              void* d_out, int out_size)
{
    const float* x        = (const float*)d_in[0];
    const float* ctx      = (const float*)d_in[1];
    const float* s_q_w    = (const float*)d_in[2];
    const float* s_kv_w   = (const float*)d_in[3];
    const float* s_proj_w = (const float*)d_in[4];
    const float* s_proj_b = (const float*)d_in[5];
    const float* s_dw_w   = (const float*)d_in[6];
    const float* s_dw_b   = (const float*)d_in[7];
    const float* t_q_w    = (const float*)d_in[8];
    const float* t_kv_w   = (const float*)d_in[9];
    const float* t_proj_w = (const float*)d_in[10];
    const float* t_proj_b = (const float*)d_in[11];
    const float* t_cw     = (const float*)d_in[12];
    const float* g_w1     = (const float*)d_in[13];
    const float* g_bn_g   = (const float*)d_in[14];
    const float* g_bn_b   = (const float*)d_in[15];
    const float* g_w2     = (const float*)d_in[16];
    const float* g_b2     = (const float*)d_in[17];
    float* out = (float*)d_out;

    float *sq, *skv, *tq, *tkv, *vloc, *f1r, *f1i, *f2r, *f2i, *f3r, *f3i;
    float *spre, *xat, *fuse, *hbuf, *gate;
    cudaGetSymbolAddress((void**)&sq,   g_sq);
    cudaGetSymbolAddress((void**)&skv,  g_skv);
    cudaGetSymbolAddress((void**)&tq,   g_tq);
    cudaGetSymbolAddress((void**)&tkv,  g_tkv);
    cudaGetSymbolAddress((void**)&vloc, g_vloc);
    cudaGetSymbolAddress((void**)&f1r,  g_f1r);
    cudaGetSymbolAddress((void**)&f1i,  g_f1i);
    cudaGetSymbolAddress((void**)&f2r,  g_f2r);
    cudaGetSymbolAddress((void**)&f2i,  g_f2i);
    cudaGetSymbolAddress((void**)&f3r,  g_f3r);
    cudaGetSymbolAddress((void**)&f3i,  g_f3i);
    cudaGetSymbolAddress((void**)&spre, g_spre);
    cudaGetSymbolAddress((void**)&xat,  g_xat);
    cudaGetSymbolAddress((void**)&fuse, g_fusb);
    cudaGetSymbolAddress((void**)&hbuf, g_hbuf);
    cudaGetSymbolAddress((void**)&gate, g_gate);

    dim3 blk256(256), blk128(128);
    dim3 gC(256, Bb);            // per (channel, batch) image kernels
    dim3 gG4(49, 4, Bb);         // gemm O=256
    dim3 gG8(49, 8, Bb);         // gemm O=512
    long nEl = TOT;
    dim3 gEl((unsigned)((nEl + 255) / 256));

    // ---- spectral branch ----
    gemm_k<<<gG4, blk256>>>(s_q_w, x, sq, nullptr, 256, CN, CN);
    gemm_k<<<gG8, blk256>>>(s_kv_w, ctx, skv, nullptr, 256, CN, C2N);
    dwconv_k<<<gC, blk256>>>(skv, s_dw_w, s_dw_b, vloc);
    dftW_r2c_k<<<gC, blk256>>>(sq, CN, f1r, f1i);
    dftH_c2c_k<<<gC, blk256>>>(f1r, f1i, f2r, f2i);
    dftW_r2c_k<<<gC, blk256>>>(skv, C2N, f1r, f1i);      // k half
    dftH_c2c_k<<<gC, blk256>>>(f1r, f1i, f3r, f3i);
    cmul_k<<<gEl, blk256>>>(f2r, f2i, f3r, f3i, nEl);
    dftW_c2c_inv_k<<<gC, blk256>>>(f2r, f2i, f1r, f1i);
    spec_final_k<<<gC, blk256>>>(f1r, f1i, skv, vloc, spre);
    gemm_k<<<gG4, blk256>>>(s_proj_w, spre, fuse, s_proj_b, 256, CN, C2N);

    // ---- token branch ----
    gemm_k<<<gG4, blk256>>>(t_q_w, x, tq, nullptr, 256, CN, CN);
    gemm_k<<<gG8, blk256>>>(t_kv_w, ctx, tkv, nullptr, 256, CN, C2N);
    flash_k<<<dim3(25, 8, Bb), blk128>>>(tq, tkv, xat);
    dftW_r2c_k<<<gC, blk256>>>(tkv + CN, C2N, f1r, f1i); // v_img
    dftH_c2c_k<<<gC, blk256>>>(f1r, f1i, f2r, f2i);
    twmul_k<<<gC, blk256>>>(f2r, f2i, t_cw);
    dftW_c2c_inv_k<<<gC, blk256>>>(f2r, f2i, f1r, f1i);
    token_final_k<<<gC, blk256>>>(f1r, f1i, xat);        // += into x_attn
    gemm_k<<<gG4, blk256>>>(t_proj_w, xat, fuse + CN, t_proj_b, 256, CN, C2N);

    // ---- fuse ----
    gemm_k<<<gG4, blk256>>>(g_w1, fuse, hbuf, nullptr, 512, C2N, CN);
    gate_k<<<dim3(25, Bb), blk128>>>(hbuf, g_bn_g, g_bn_b, g_w2, g_b2, gate);
    blend_k<<<gEl, blk256>>>(fuse, gate, out);
}

// round 8
// speedup vs baseline: 2.2167x; 2.2167x over previous
#include <cuda_runtime.h>
#include <cuda_bf16.h>
#include <stdint.h>
#include <math.h>

#define NP 3136
#define Bb 2
#define CN 802816L
#define C2N 1605632L
#define TOT 1605632L
#define HT 1792            // 56*32 padded half-spectrum elems per image
#define CHT 458752L        // 256*HT
#define NPH 1568           // NP/2 (bf16 pairs per row)

// ---------------- scratch ----------------
static __device__ float g_sq  [TOT];
static __device__ float g_skv [Bb*C2N];
static __device__ float g_tq  [TOT];
static __device__ float g_tkv [Bb*C2N];
static __device__ float g_vloc[TOT];
static __device__ float g_spre[TOT];
static __device__ float g_xat [TOT];
static __device__ float g_fusb[Bb*C2N];
static __device__ float g_hbuf[TOT];
static __device__ float g_gate[Bb*NP];
static __device__ float2 g_sp1 [Bb*CHT];
static __device__ float2 g_sp2 [Bb*CHT];
static __device__ float2 g_sp3 [Bb*CHT];
static __device__ __nv_bfloat162 g_qb[Bb*8L*NP*16];   // [b][h][n][d/2]
static __device__ __nv_bfloat162 g_kb[Bb*8L*NP*16];
static __device__ __nv_bfloat162 g_vb[Bb*256L*NPH];   // [b][c][n/2]

// ---------------- tiled SGEMM ----------------
__global__ void gemm_k(const float* __restrict__ W, const float* __restrict__ X,
                       float* __restrict__ Y, const float* __restrict__ bias,
                       int I, long xB, long yB)
{
    __shared__ float Ws[64][17];
    __shared__ float Xs[16][64];
    int tid = threadIdx.x, tx = tid & 15, ty = tid >> 4;
    int nb = blockIdx.x * 64, ob = blockIdx.y * 64;
    const float* Xb = X + (long)blockIdx.z * xB;
    float*       Yb = Y + (long)blockIdx.z * yB;
    float acc[4][4];
#pragma unroll
    for (int i = 0; i < 4; i++)
#pragma unroll
        for (int j = 0; j < 4; j++) acc[i][j] = 0.f;
    for (int kt = 0; kt < I; kt += 16) {
#pragma unroll
        for (int l = 0; l < 4; l++) {
            int idx = l * 256 + tid;
            Ws[idx >> 4][idx & 15] = W[(long)(ob + (idx >> 4)) * I + kt + (idx & 15)];
            Xs[idx >> 6][idx & 63] = Xb[(long)(kt + (idx >> 6)) * NP + nb + (idx & 63)];
        }
        __syncthreads();
#pragma unroll
        for (int kk = 0; kk < 16; kk++) {
            float4 b4 = *(const float4*)&Xs[kk][tx * 4];
            float bv[4] = {b4.x, b4.y, b4.z, b4.w};
            float av[4] = {Ws[ty*4+0][kk], Ws[ty*4+1][kk], Ws[ty*4+2][kk], Ws[ty*4+3][kk]};
#pragma unroll
            for (int i = 0; i < 4; i++)
#pragma unroll
                for (int j = 0; j < 4; j++)
                    acc[i][j] = fmaf(av[i], bv[j], acc[i][j]);
        }
        __syncthreads();
    }
#pragma unroll
    for (int i = 0; i < 4; i++) {
        int o = ob + ty * 4 + i;
        float bs = bias ? bias[o] : 0.f;
#pragma unroll
        for (int j = 0; j < 4; j++)
            Yb[(long)o * NP + nb + tx * 4 + j] = acc[i][j] + bs;
    }
}

// ---------------- depthwise 3x3 ----------------
__global__ void dwconv_k(const float* __restrict__ KV, const float* __restrict__ w,
                         const float* __restrict__ bias, float* __restrict__ out)
{
    int c = blockIdx.x, b = blockIdx.y;
    __shared__ float vs[NP];
    const float* vp = KV + ((long)b * 512 + 256 + c) * NP;
    for (int i = threadIdx.x; i < NP; i += 256) vs[i] = vp[i];
    __syncthreads();
    float wr[9];
#pragma unroll
    for (int i = 0; i < 9; i++) wr[i] = w[c * 9 + i];
    float bsv = bias[c];
    long ob = ((long)b * 256 + c) * NP;
    for (int o = threadIdx.x; o < NP; o += 256) {
        int y = o / 56, x = o % 56;
        float acc = bsv;
#pragma unroll
        for (int dy = -1; dy <= 1; dy++) {
            int yy = y + dy;
            if ((unsigned)yy >= 56u) continue;
#pragma unroll
            for (int dx = -1; dx <= 1; dx++) {
                int xx = x + dx;
                if ((unsigned)xx >= 56u) continue;
                acc += wr[(dy + 1) * 3 + dx + 1] * vs[yy * 56 + xx];
            }
        }
        out[ob + o] = acc;
    }
}

// ---------------- DFT: W-axis r2c (half spectrum, kx<29), conflict-free twiddles --------
// out[r][k] = sum_n in[r][n] e^{-2pi i k n/56}. grid(256,Bb), block 256
__global__ void r2cw_k(const float* __restrict__ in, long inB, float2* __restrict__ out)
{
    __shared__ float xs[NP];
    __shared__ float2 tw[HT];            // [n][k] transposed: lanes read consecutive k
    for (int i = threadIdx.x; i < HT; i += 256) {
        int n = i >> 5, k = i & 31;
        float c = 0.f, s = 0.f;
        if (k < 29) { int m = (n * k) % 56; sincospif(2.f * (float)m / 56.f, &s, &c); }
        tw[i] = make_float2(c, s);
    }
    const float* ib = in + (long)blockIdx.y * inB + (long)blockIdx.x * NP;
    for (int i = threadIdx.x; i < NP; i += 256) xs[i] = ib[i];
    __syncthreads();
    long base = ((long)blockIdx.y * 256 + blockIdx.x) * HT;
    for (int o = threadIdx.x; o < HT; o += 256) {
        int r = o >> 5, k = o & 31;
        if (k >= 29) continue;
        const float* xr = xs + r * 56;
        float ac = 0.f, as = 0.f;
#pragma unroll 14
        for (int n = 0; n < 56; n++) {
            float2 w = tw[n * 32 + k];
            float v = xr[n];
            ac = fmaf(v, w.x, ac);
            as = fmaf(v, w.y, as);
        }
        out[base + o] = make_float2(ac, -as);
    }
}

// ---------------- DFT: H-axis c2c on 29 cols (sign folded into twiddle table) ----------
// out[kh][kx] = sum_r in[r][kx] * e^{-sg*2pi i kh r/56}. grid(256,Bb)
__global__ void c2ch_k(const float2* __restrict__ in, float2* __restrict__ out, float sg)
{
    __shared__ float2 xc[HT];
    __shared__ float2 tw[NP];            // [r][kh], broadcast across warp
    for (int i = threadIdx.x; i < NP; i += 256) {
        int r = i / 56, kh = i % 56;
        int m = (r * kh) % 56;
        float c, s; sincospif(2.f * (float)m / 56.f, &s, &c);
        tw[i] = make_float2(c, sg * s);
    }
    long base = ((long)blockIdx.y * 256 + blockIdx.x) * HT;
    for (int i = threadIdx.x; i < HT; i += 256) xc[i] = in[base + i];
    __syncthreads();
    for (int o = threadIdx.x; o < HT; o += 256) {
        int kh = o >> 5, kx = o & 31;
        if (kx >= 29) continue;
        float pr = 0.f, pi = 0.f;
#pragma unroll 14
        for (int r = 0; r < 56; r++) {
            float2 w = tw[r * 56 + kh];
            float2 v = xc[r * 32 + kx];
            pr = fmaf(v.x, w.x, fmaf(v.y, w.y, pr));
            pi = fmaf(v.y, w.x, fmaf(-v.x, w.y, pi));
        }
        out[base + o] = make_float2(pr, pi);
    }
}

// ---------------- c2r along W (half-sum with mult) + spectral epilogue -----------------
__global__ void c2r_spec_k(const float2* __restrict__ in, const float* __restrict__ KV,
                           const float* __restrict__ vloc, float* __restrict__ out)
{
    __shared__ float2 xc[HT];
    __shared__ float2 tw[29 * 56];       // [k][x]: (mult*cos, -mult*sin)
    for (int i = threadIdx.x; i < 29 * 56; i += 256) {
        int k = i / 56, x = i % 56;
        int m = (k * x) % 56;
        float c, s; sincospif(2.f * (float)m / 56.f, &s, &c);
        float mult = (k == 0 || k == 28) ? 1.f : 2.f;
        tw[i] = make_float2(mult * c, -mult * s);
    }
    int c = blockIdx.x, b = blockIdx.y;
    long base = ((long)b * 256 + c) * HT;
    for (int i = threadIdx.x; i < HT; i += 256) xc[i] = in[base + i];
    __syncthreads();
    const float* vp = KV + ((long)b * 512 + 256 + c) * NP;
    long ob = ((long)b * 256 + c) * NP;
    const float sc = 1.0f / 175616.0f;   // 1/N^{3/2}
    for (int o = threadIdx.x; o < NP; o += 256) {
        int r = o / 56, x = o % 56;
        float acc = 0.f;
#pragma unroll
        for (int k = 0; k < 29; k++) {
            float2 w = tw[k * 56 + x];
            float2 v = xc[r * 32 + k];
            acc = fmaf(v.x, w.x, fmaf(v.y, w.y, acc));
        }
        out[ob + o] = (sc * acc) * vp[o] + vloc[ob + o];
    }
}

// ---------------- c2r along W + token epilogue (+= into x_attn) ------------------------
__global__ void c2r_token_k(const float2* __restrict__ in, float* __restrict__ out)
{
    __shared__ float2 xc[HT];
    __shared__ float2 tw[29 * 56];
    for (int i = threadIdx.x; i < 29 * 56; i += 256) {
        int k = i / 56, x = i % 56;
        int m = (k * x) % 56;
        float c, s; sincospif(2.f * (float)m / 56.f, &s, &c);
        float mult = (k == 0 || k == 28) ? 1.f : 2.f;
        tw[i] = make_float2(mult * c, -mult * s);
    }
    long base = ((long)blockIdx.y * 256 + blockIdx.x) * HT;
    for (int i = threadIdx.x; i < HT; i += 256) xc[i] = in[base + i];
    __syncthreads();
    long ob = ((long)blockIdx.y * 256 + blockIdx.x) * NP;
    const float sc = 1.0f / 3136.0f;
    for (int o = threadIdx.x; o < NP; o += 256) {
        int r = o / 56, x = o % 56;
        float acc = 0.f;
#pragma unroll
        for (int k = 0; k < 29; k++) {
            float2 w = tw[k * 56 + x];
            float2 v = xc[r * 32 + k];
            acc = fmaf(v.x, w.x, fmaf(v.y, w.y, acc));
        }
        out[ob + o] += sc * acc;
    }
}

// ---------------- complex pointwise a *= b (padded half spectra; pads are 0) ----------
__global__ void cmulh_k(float2* __restrict__ a, const float2* __restrict__ b, long n)
{
    long i = (long)blockIdx.x * blockDim.x + threadIdx.x;
    if (i < n) {
        float2 av = a[i], bv = b[i];
        a[i] = make_float2(av.x * bv.x - av.y * bv.y, av.x * bv.y + av.y * bv.x);
    }
}

// ---------------- token spectral weight (direct half-spectrum, no extension) ----------
__global__ void twmulh_k(float2* __restrict__ f, const float* __restrict__ cw)
{
    int c = blockIdx.x, b = blockIdx.y;
    long base = ((long)b * 256 + c) * HT;
    for (int o = threadIdx.x; o < HT; o += 256) {
        int kx = o & 31;
        if (kx >= 29) continue;
        int ky = o >> 5;
        long wb = (((long)c * 56 + ky) * 29 + kx) * 2;
        float wr = cw[wb], wi = cw[wb + 1];
        float2 v = f[base + o];
        f[base + o] = make_float2(v.x * wr - v.y * wi, v.x * wi + v.y * wr);
    }
}

// ---------------- bf16 conversion/transpose kernels -----------------------------------
// dst[b][h][n][d/2] pairs from src[b][h*32+d][n]; scale folded (Q) or 1 (K)
__global__ void cvtqk_k(const float* __restrict__ src, long bstride,
                        __nv_bfloat162* __restrict__ dst, float scale)
{
    long i = (long)blockIdx.x * blockDim.x + threadIdx.x;
    if (i >= (long)Bb * 8 * NP * 16) return;
    int p = (int)(i & 15);
    long t = i >> 4;
    int n = (int)(t % NP);
    long t2 = t / NP;
    int h = (int)(t2 & 7), b = (int)(t2 >> 3);
    long s0 = (long)b * bstride + (long)(h * 32 + 2 * p) * NP + n;
    dst[i] = __floats2bfloat162_rn(src[s0] * scale, src[s0 + NP] * scale);
}

// dst[b][c][n/2] pairs from v-half of tkv
__global__ void cvtv_k(const float* __restrict__ tkv, __nv_bfloat162* __restrict__ dst)
{
    long i = (long)blockIdx.x * blockDim.x + threadIdx.x;
    if (i >= (long)Bb * 256 * NPH) return;
    int n2 = (int)(i % NPH);
    long cr = i / NPH;
    int b = (int)(cr >> 8), c = (int)(cr & 255);
    long s = (long)b * C2N + CN + (long)c * NP + 2 * n2;
    dst[i] = __floats2bfloat162_rn(tkv[s], tkv[s + 1]);
}

// ---------------- tensor-core flash attention ------------------------------------------
__device__ __forceinline__ void mma16816(float* c, const uint32_t* a, const uint32_t* b)
{
    asm volatile("mma.sync.aligned.m16n8k16.row.col.f32.bf16.bf16.f32 "
                 "{%0,%1,%2,%3}, {%4,%5,%6,%7}, {%8,%9}, {%0,%1,%2,%3};"
                 : "+f"(c[0]), "+f"(c[1]), "+f"(c[2]), "+f"(c[3])
                 : "r"(a[0]), "r"(a[1]), "r"(a[2]), "r"(a[3]), "r"(b[0]), "r"(b[1]));
}

__device__ __forceinline__ uint32_t packbf(float lo, float hi)
{
    __nv_bfloat162 h = __floats2bfloat162_rn(lo, hi);
    return *(uint32_t*)&h;
}

// grid(25, 8, Bb), block 256 (8 warps, 16 queries/warp)
__global__ void flash_mma_k(const __nv_bfloat162* __restrict__ Qb,
                            const __nv_bfloat162* __restrict__ Kb,
                            const __nv_bfloat162* __restrict__ Vb,
                            float* __restrict__ O)
{
    int b = blockIdx.z, h = blockIdx.y;
    int warp = threadIdx.x >> 5, lane = threadIdx.x & 31;
    int g = lane >> 2, j = lane & 3;
    int q0 = blockIdx.x * 128 + warp * 16;
    if (q0 >= NP) return;
    const uint32_t* Qh = (const uint32_t*)(Qb + (long)(b * 8 + h) * NP * 16);
    const uint32_t* Kh = (const uint32_t*)(Kb + (long)(b * 8 + h) * NP * 16);
    const uint32_t* Vh = (const uint32_t*)(Vb + (long)(b * 256 + h * 32) * NPH);

    uint32_t qa[2][4];
#pragma unroll
    for (int kc = 0; kc < 2; kc++) {
        qa[kc][0] = Qh[(q0 + g)     * 16 + kc * 8 + j];
        qa[kc][1] = Qh[(q0 + g + 8) * 16 + kc * 8 + j];
        qa[kc][2] = Qh[(q0 + g)     * 16 + kc * 8 + j + 4];
        qa[kc][3] = Qh[(q0 + g + 8) * 16 + kc * 8 + j + 4];
    }

    float o_[4][4];
#pragma unroll
    for (int d = 0; d < 4; d++)
#pragma unroll
        for (int r = 0; r < 4; r++) o_[d][r] = 0.f;
    float mlo = -1e30f, mhi = -1e30f, llo = 0.f, lhi = 0.f;

#pragma unroll 1
    for (int kt = 0; kt < 196; kt++) {
        int kb = kt * 16;
        uint32_t kf[2][2][2];
#pragma unroll
        for (int nc = 0; nc < 2; nc++) {
            int key = kb + nc * 8 + g;
#pragma unroll
            for (int kc = 0; kc < 2; kc++) {
                kf[nc][kc][0] = Kh[key * 16 + kc * 8 + j];
                kf[nc][kc][1] = Kh[key * 16 + kc * 8 + j + 4];
            }
        }
        float s0[4] = {0.f, 0.f, 0.f, 0.f}, s1[4] = {0.f, 0.f, 0.f, 0.f};
        mma16816(s0, qa[0], kf[0][0]); mma16816(s0, qa[1], kf[0][1]);
        mma16816(s1, qa[0], kf[1][0]); mma16816(s1, qa[1], kf[1][1]);

        float tlo = fmaxf(fmaxf(s0[0], s0[1]), fmaxf(s1[0], s1[1]));
        float thi = fmaxf(fmaxf(s0[2], s0[3]), fmaxf(s1[2], s1[3]));
        tlo = fmaxf(tlo, __shfl_xor_sync(0xffffffff, tlo, 1));
        tlo = fmaxf(tlo, __shfl_xor_sync(0xffffffff, tlo, 2));
        thi = fmaxf(thi, __shfl_xor_sync(0xffffffff, thi, 1));
        thi = fmaxf(thi, __shfl_xor_sync(0xffffffff, thi, 2));
        float mnlo = fmaxf(mlo, tlo), mnhi = fmaxf(mhi, thi);
        float clo = __expf(mlo - mnlo), chi = __expf(mhi - mnhi);

        float p00 = __expf(s0[0] - mnlo), p01 = __expf(s0[1] - mnlo);
        float p02 = __expf(s0[2] - mnhi), p03 = __expf(s0[3] - mnhi);
        float p10 = __expf(s1[0] - mnlo), p11 = __expf(s1[1] - mnlo);
        float p12 = __expf(s1[2] - mnhi), p13 = __expf(s1[3] - mnhi);

        float sumlo = p00 + p01 + p10 + p11;
        float sumhi = p02 + p03 + p12 + p13;
        sumlo += __shfl_xor_sync(0xffffffff, sumlo, 1);
        sumlo += __shfl_xor_sync(0xffffffff, sumlo, 2);
        sumhi += __shfl_xor_sync(0xffffffff, sumhi, 1);
        sumhi += __shfl_xor_sync(0xffffffff, sumhi, 2);
        llo = llo * clo + sumlo;
        lhi = lhi * chi + sumhi;
#pragma unroll
        for (int d = 0; d < 4; d++) {
            o_[d][0] *= clo; o_[d][1] *= clo;
            o_[d][2] *= chi; o_[d][3] *= chi;
        }
        mlo = mnlo; mhi = mnhi;

        uint32_t pa[4];
        pa[0] = packbf(p00, p01);
        pa[1] = packbf(p02, p03);
        pa[2] = packbf(p10, p11);
        pa[3] = packbf(p12, p13);

#pragma unroll
        for (int dc = 0; dc < 4; dc++) {
            uint32_t vf[2];
            long vrow = (long)(dc * 8 + g) * NPH + (kb >> 1) + j;
            vf[0] = Vh[vrow];
            vf[1] = Vh[vrow + 4];
            mma16816(o_[dc], pa, vf);
        }
    }

    float invlo = 1.f / llo, invhi = 1.f / lhi;
#pragma unroll
    for (int dc = 0; dc < 4; dc++) {
        long d0 = (long)(b * 256 + h * 32 + dc * 8 + 2 * j) * NP;
        O[d0 + q0 + g]            = o_[dc][0] * invlo;
        O[d0 + NP + q0 + g]       = o_[dc][1] * invlo;
        O[d0 + q0 + g + 8]        = o_[dc][2] * invhi;
        O[d0 + NP + q0 + g + 8]   = o_[dc][3] * invhi;
    }
}

// ---------------- fuse ----------------
__global__ void gate_k(const float* __restrict__ hraw, const float* __restrict__ gam,
                       const float* __restrict__ bet, const float* __restrict__ w2,
                       const float* __restrict__ b2p, float* __restrict__ gate)
{
    int b = blockIdx.y;
    int n = blockIdx.x * 128 + threadIdx.x;
    if (n >= NP) return;
    const float inv = rsqrtf(1.f + 1e-5f);
    const float* hb = hraw + (long)b * CN + n;
    float g = b2p[0];
#pragma unroll 8
    for (int c = 0; c < 256; c++) {
        float hv = hb[(long)c * NP] * inv * gam[c] + bet[c];
        g = fmaf(w2[c], fmaxf(hv, 0.f), g);
    }
    gate[(long)b * NP + n] = 1.f / (1.f + __expf(-g));
}

__global__ void blend_k(const float* __restrict__ fuse, const float* __restrict__ gate,
                        float* __restrict__ out)
{
    long i = (long)blockIdx.x * blockDim.x + threadIdx.x;
    if (i >= TOT) return;
    long b = i / CN;
    long n = i % NP;
    float g = gate[b * NP + n];
    long fidx = i + b * CN;
    out[i] = g * fuse[fidx] + (1.f - g) * fuse[fidx + CN];
}

extern "C" void kernel_launch(void* const* d_in, const int* in_sizes, int n_in,
                              void* d_out, int out_size)
{
    const float* x        = (const float*)d_in[0];
    const float* ctx      = (const float*)d_in[1];
    const float* s_q_w    = (const float*)d_in[2];
    const float* s_kv_w   = (const float*)d_in[3];
    const float* s_proj_w = (const float*)d_in[4];
    const float* s_proj_b = (const float*)d_in[5];
    const float* s_dw_w   = (const float*)d_in[6];
    const float* s_dw_b   = (const float*)d_in[7];
    const float* t_q_w    = (const float*)d_in[8];
    const float* t_kv_w   = (const float*)d_in[9];
    const float* t_proj_w = (const float*)d_in[10];
    const float* t_proj_b = (const float*)d_in[11];
    const float* t_cw     = (const float*)d_in[12];
    const float* g_w1     = (const float*)d_in[13];
    const float* g_bn_g   = (const float*)d_in[14];
    const float* g_bn_b   = (const float*)d_in[15];
    const float* g_w2     = (const float*)d_in[16];
    const float* g_b2     = (const float*)d_in[17];
    float* out = (float*)d_out;

    float *sq, *skv, *tq, *tkv, *vloc, *spre, *xat, *fuse, *hbuf, *gate;
    float2 *sp1, *sp2, *sp3;
    __nv_bfloat162 *qb, *kb, *vb;
    cudaGetSymbolAddress((void**)&sq,   g_sq);
    cudaGetSymbolAddress((void**)&skv,  g_skv);
    cudaGetSymbolAddress((void**)&tq,   g_tq);
    cudaGetSymbolAddress((void**)&tkv,  g_tkv);
    cudaGetSymbolAddress((void**)&vloc, g_vloc);
    cudaGetSymbolAddress((void**)&spre, g_spre);
    cudaGetSymbolAddress((void**)&xat,  g_xat);
    cudaGetSymbolAddress((void**)&fuse, g_fusb);
    cudaGetSymbolAddress((void**)&hbuf, g_hbuf);
    cudaGetSymbolAddress((void**)&gate, g_gate);
    cudaGetSymbolAddress((void**)&sp1,  g_sp1);
    cudaGetSymbolAddress((void**)&sp2,  g_sp2);
    cudaGetSymbolAddress((void**)&sp3,  g_sp3);
    cudaGetSymbolAddress((void**)&qb,   g_qb);
    cudaGetSymbolAddress((void**)&kb,   g_kb);
    cudaGetSymbolAddress((void**)&vb,   g_vb);

    const float SCALE = 0.17677669529663687f;
    dim3 blk256(256), blk128(128);
    dim3 gC(256, Bb);
    dim3 gG4(49, 4, Bb);
    dim3 gG8(49, 8, Bb);
    long nHalf = (long)Bb * CHT;

    // ---- spectral branch ----
    gemm_k<<<gG4, blk256>>>(s_q_w, x, sq, nullptr, 256, CN, CN);
    gemm_k<<<gG8, blk256>>>(s_kv_w, ctx, skv, nullptr, 256, CN, C2N);
    dwconv_k<<<gC, blk256>>>(skv, s_dw_w, s_dw_b, vloc);
    r2cw_k<<<gC, blk256>>>(sq, CN, sp1);
    c2ch_k<<<gC, blk256>>>(sp1, sp2, 1.f);
    r2cw_k<<<gC, blk256>>>(skv, C2N, sp1);            // k half
    c2ch_k<<<gC, blk256>>>(sp1, sp3, 1.f);
    cmulh_k<<<dim3((unsigned)((nHalf + 255) / 256)), blk256>>>(sp2, sp3, nHalf);
    c2ch_k<<<gC, blk256>>>(sp2, sp1, -1.f);
    c2r_spec_k<<<gC, blk256>>>(sp1, skv, vloc, spre);
    gemm_k<<<gG4, blk256>>>(s_proj_w, spre, fuse, s_proj_b, 256, CN, C2N);

    // ---- token branch ----
    gemm_k<<<gG4, blk256>>>(t_q_w, x, tq, nullptr, 256, CN, CN);
    gemm_k<<<gG8, blk256>>>(t_kv_w, ctx, tkv, nullptr, 256, CN, C2N);
    cvtqk_k<<<dim3(3136), blk256>>>(tq, CN, qb, SCALE);
    cvtqk_k<<<dim3(3136), blk256>>>(tkv, C2N, kb, 1.f);
    cvtv_k<<<dim3(3136), blk256>>>(tkv, vb);
    flash_mma_k<<<dim3(25, 8, Bb), blk256>>>(qb, kb, vb, xat);
    r2cw_k<<<gC, blk256>>>(tkv + CN, C2N, sp1);       // v_img
    c2ch_k<<<gC, blk256>>>(sp1, sp2, 1.f);
    twmulh_k<<<gC, blk256>>>(sp2, t_cw);
    c2ch_k<<<gC, blk256>>>(sp2, sp1, -1.f);
    c2r_token_k<<<gC, blk256>>>(sp1, xat);            // += into x_attn
    gemm_k<<<gG4, blk256>>>(t_proj_w, xat, fuse + CN, t_proj_b, 256, CN, C2N);

    // ---- fuse ----
    gemm_k<<<gG4, blk256>>>(g_w1, fuse, hbuf, nullptr, 512, C2N, CN);
    gate_k<<<dim3(25, Bb), blk128>>>(hbuf, g_bn_g, g_bn_b, g_w2, g_b2, gate);
    blend_k<<<dim3((unsigned)((TOT + 255) / 256)), blk256>>>(fuse, gate, out);
}

// round 9
// speedup vs baseline: 2.4242x; 1.0936x over previous
#include <cuda_runtime.h>
#include <cuda_bf16.h>
#include <stdint.h>
#include <math.h>

#define NP 3136
#define Bb 2
#define CN 802816L
#define C2N 1605632L
#define TOT 1605632L
#define HT 1792            // 56*32 padded half-spectrum elems per image
#define CHT 458752L        // 256*HT
#define NPH 1568           // NP/2 (bf16 pairs per row)

// ---------------- scratch ----------------
static __device__ float g_sq  [TOT];
static __device__ float g_skv [Bb*C2N];
static __device__ float g_tq  [TOT];
static __device__ float g_tkv [Bb*C2N];
static __device__ float g_vloc[TOT];
static __device__ float g_spre[TOT];
static __device__ float g_xat [TOT];
static __device__ float g_fusb[Bb*C2N];
static __device__ float g_hbuf[TOT];
static __device__ float g_gate[Bb*NP];
static __device__ float2 g_sp1 [Bb*CHT];
static __device__ float2 g_sp2 [Bb*CHT];
static __device__ float2 g_sp3 [Bb*CHT];
static __device__ __nv_bfloat162 g_qb[Bb*8L*NP*16];   // [b][h][n][d/2]
static __device__ __nv_bfloat162 g_kb[Bb*8L*NP*16];
static __device__ __nv_bfloat162 g_vb[Bb*256L*NPH];   // [b][c][n/2]

// ---------------- TF32 tensor-core GEMM ----------------
// Y[b][o][n] = sum_i W[o][i]*X[b][i][n] (+bias); tile 128o x 64n, block 256 (8 warps)
__device__ __forceinline__ float tf32r(float x)
{
    uint32_t u;
    asm("cvt.rna.tf32.f32 %0, %1;" : "=r"(u) : "f"(x));
    return __uint_as_float(u);
}

__device__ __forceinline__ void mma_tf32(float* c, const uint32_t* a, const uint32_t* b)
{
    asm volatile("mma.sync.aligned.m16n8k8.row.col.f32.tf32.tf32.f32 "
                 "{%0,%1,%2,%3}, {%4,%5,%6,%7}, {%8,%9}, {%0,%1,%2,%3};"
                 : "+f"(c[0]), "+f"(c[1]), "+f"(c[2]), "+f"(c[3])
                 : "r"(a[0]), "r"(a[1]), "r"(a[2]), "r"(a[3]), "r"(b[0]), "r"(b[1]));
}

__global__ void gemm_tf32_k(const float* __restrict__ W, const float* __restrict__ X,
                            float* __restrict__ Y, const float* __restrict__ bias,
                            int I, long xB, long yB)
{
    __shared__ float Ws[128][20];
    __shared__ float Xs[16][65];
    int tid = threadIdx.x;
    int warp = tid >> 5, lane = tid & 31;
    int g = lane >> 2, j = lane & 3;
    int warp_o = warp & 3, warp_n = warp >> 2;       // 4 x 2 warps -> 128o x 64n
    int nb = blockIdx.x * 64, ob = blockIdx.y * 128;
    const float* Xb = X + (long)blockIdx.z * xB;
    float*       Yb = Y + (long)blockIdx.z * yB;

    float acc[2][4][4];
#pragma unroll
    for (int mo = 0; mo < 2; mo++)
#pragma unroll
        for (int nn = 0; nn < 4; nn++)
#pragma unroll
            for (int r = 0; r < 4; r++) acc[mo][nn][r] = 0.f;

    int wrow = tid >> 1, whf = (tid & 1) * 8;        // W tile: 128 rows x 16
    int xrow = tid >> 4, xc4 = (tid & 15) * 4;       // X tile: 16 rows x 64

    for (int kt = 0; kt < I; kt += 16) {
        float4 w0 = *(const float4*)&W[(long)(ob + wrow) * I + kt + whf];
        float4 w1 = *(const float4*)&W[(long)(ob + wrow) * I + kt + whf + 4];
        Ws[wrow][whf + 0] = tf32r(w0.x); Ws[wrow][whf + 1] = tf32r(w0.y);
        Ws[wrow][whf + 2] = tf32r(w0.z); Ws[wrow][whf + 3] = tf32r(w0.w);
        Ws[wrow][whf + 4] = tf32r(w1.x); Ws[wrow][whf + 5] = tf32r(w1.y);
        Ws[wrow][whf + 6] = tf32r(w1.z); Ws[wrow][whf + 7] = tf32r(w1.w);
        float4 xv = *(const float4*)&Xb[(long)(kt + xrow) * NP + nb + xc4];
        Xs[xrow][xc4 + 0] = tf32r(xv.x); Xs[xrow][xc4 + 1] = tf32r(xv.y);
        Xs[xrow][xc4 + 2] = tf32r(xv.z); Xs[xrow][xc4 + 3] = tf32r(xv.w);
        __syncthreads();
#pragma unroll
        for (int kk = 0; kk < 16; kk += 8) {
            uint32_t a[2][4], b[4][2];
#pragma unroll
            for (int mo = 0; mo < 2; mo++) {
                int r0 = warp_o * 32 + mo * 16 + g;
                a[mo][0] = __float_as_uint(Ws[r0][kk + j]);
                a[mo][1] = __float_as_uint(Ws[r0 + 8][kk + j]);
                a[mo][2] = __float_as_uint(Ws[r0][kk + j + 4]);
                a[mo][3] = __float_as_uint(Ws[r0 + 8][kk + j + 4]);
            }
#pragma unroll
            for (int nn = 0; nn < 4; nn++) {
                int cc = warp_n * 32 + nn * 8 + g;
                b[nn][0] = __float_as_uint(Xs[kk + j][cc]);
                b[nn][1] = __float_as_uint(Xs[kk + j + 4][cc]);
            }
#pragma unroll
            for (int mo = 0; mo < 2; mo++)
#pragma unroll
                for (int nn = 0; nn < 4; nn++)
                    mma_tf32(acc[mo][nn], a[mo], b[nn]);
        }
        __syncthreads();
    }

#pragma unroll
    for (int mo = 0; mo < 2; mo++) {
        int r0 = ob + warp_o * 32 + mo * 16 + g;
        float bs0 = bias ? bias[r0] : 0.f;
        float bs1 = bias ? bias[r0 + 8] : 0.f;
#pragma unroll
        for (int nn = 0; nn < 4; nn++) {
            int col = nb + warp_n * 32 + nn * 8 + j * 2;
            float2 v0 = make_float2(acc[mo][nn][0] + bs0, acc[mo][nn][1] + bs0);
            float2 v1 = make_float2(acc[mo][nn][2] + bs1, acc[mo][nn][3] + bs1);
            *(float2*)&Yb[(long)r0 * NP + col] = v0;
            *(float2*)&Yb[(long)(r0 + 8) * NP + col] = v1;
        }
    }
}

// ---------------- depthwise 3x3 ----------------
__global__ void dwconv_k(const float* __restrict__ KV, const float* __restrict__ w,
                         const float* __restrict__ bias, float* __restrict__ out)
{
    int c = blockIdx.x, b = blockIdx.y;
    __shared__ float vs[NP];
    const float* vp = KV + ((long)b * 512 + 256 + c) * NP;
    for (int i = threadIdx.x; i < NP; i += 256) vs[i] = vp[i];
    __syncthreads();
    float wr[9];
#pragma unroll
    for (int i = 0; i < 9; i++) wr[i] = w[c * 9 + i];
    float bsv = bias[c];
    long ob = ((long)b * 256 + c) * NP;
    for (int o = threadIdx.x; o < NP; o += 256) {
        int y = o / 56, x = o % 56;
        float acc = bsv;
#pragma unroll
        for (int dy = -1; dy <= 1; dy++) {
            int yy = y + dy;
            if ((unsigned)yy >= 56u) continue;
#pragma unroll
            for (int dx = -1; dx <= 1; dx++) {
                int xx = x + dx;
                if ((unsigned)xx >= 56u) continue;
                acc += wr[(dy + 1) * 3 + dx + 1] * vs[yy * 56 + xx];
            }
        }
        out[ob + o] = acc;
    }
}

// ---------------- DFT: W-axis r2c (half spectrum, kx<29) ----------------
__global__ void r2cw_k(const float* __restrict__ in, long inB, float2* __restrict__ out)
{
    __shared__ float xs[NP];
    __shared__ float2 tw[HT];
    for (int i = threadIdx.x; i < HT; i += 256) {
        int n = i >> 5, k = i & 31;
        float c = 0.f, s = 0.f;
        if (k < 29) { int m = (n * k) % 56; sincospif(2.f * (float)m / 56.f, &s, &c); }
        tw[i] = make_float2(c, s);
    }
    const float* ib = in + (long)blockIdx.y * inB + (long)blockIdx.x * NP;
    for (int i = threadIdx.x; i < NP; i += 256) xs[i] = ib[i];
    __syncthreads();
    long base = ((long)blockIdx.y * 256 + blockIdx.x) * HT;
    for (int o = threadIdx.x; o < HT; o += 256) {
        int r = o >> 5, k = o & 31;
        if (k >= 29) continue;
        const float* xr = xs + r * 56;
        float ac = 0.f, as = 0.f;
#pragma unroll 14
        for (int n = 0; n < 56; n++) {
            float2 w = tw[n * 32 + k];
            float v = xr[n];
            ac = fmaf(v, w.x, ac);
            as = fmaf(v, w.y, as);
        }
        out[base + o] = make_float2(ac, -as);
    }
}

// ---------------- DFT: H-axis c2c on 29 cols ----------------
__global__ void c2ch_k(const float2* __restrict__ in, float2* __restrict__ out, float sg)
{
    __shared__ float2 xc[HT];
    __shared__ float2 tw[NP];
    for (int i = threadIdx.x; i < NP; i += 256) {
        int r = i / 56, kh = i % 56;
        int m = (r * kh) % 56;
        float c, s; sincospif(2.f * (float)m / 56.f, &s, &c);
        tw[i] = make_float2(c, sg * s);
    }
    long base = ((long)blockIdx.y * 256 + blockIdx.x) * HT;
    for (int i = threadIdx.x; i < HT; i += 256) xc[i] = in[base + i];
    __syncthreads();
    for (int o = threadIdx.x; o < HT; o += 256) {
        int kh = o >> 5, kx = o & 31;
        if (kx >= 29) continue;
        float pr = 0.f, pi = 0.f;
#pragma unroll 14
        for (int r = 0; r < 56; r++) {
            float2 w = tw[r * 56 + kh];
            float2 v = xc[r * 32 + kx];
            pr = fmaf(v.x, w.x, fmaf(v.y, w.y, pr));
            pi = fmaf(v.y, w.x, fmaf(-v.x, w.y, pi));
        }
        out[base + o] = make_float2(pr, pi);
    }
}

// ---------------- c2r along W + spectral epilogue ----------------
__global__ void c2r_spec_k(const float2* __restrict__ in, const float* __restrict__ KV,
                           const float* __restrict__ vloc, float* __restrict__ out)
{
    __shared__ float2 xc[HT];
    __shared__ float2 tw[29 * 56];
    for (int i = threadIdx.x; i < 29 * 56; i += 256) {
        int k = i / 56, x = i % 56;
        int m = (k * x) % 56;
        float c, s; sincospif(2.f * (float)m / 56.f, &s, &c);
        float mult = (k == 0 || k == 28) ? 1.f : 2.f;
        tw[i] = make_float2(mult * c, -mult * s);
    }
    int c = blockIdx.x, b = blockIdx.y;
    long base = ((long)b * 256 + c) * HT;
    for (int i = threadIdx.x; i < HT; i += 256) xc[i] = in[base + i];
    __syncthreads();
    const float* vp = KV + ((long)b * 512 + 256 + c) * NP;
    long ob = ((long)b * 256 + c) * NP;
    const float sc = 1.0f / 175616.0f;
    for (int o = threadIdx.x; o < NP; o += 256) {
        int r = o / 56, x = o % 56;
        float acc = 0.f;
#pragma unroll
        for (int k = 0; k < 29; k++) {
            float2 w = tw[k * 56 + x];
            float2 v = xc[r * 32 + k];
            acc = fmaf(v.x, w.x, fmaf(v.y, w.y, acc));
        }
        out[ob + o] = (sc * acc) * vp[o] + vloc[ob + o];
    }
}

// ---------------- c2r along W + token epilogue ----------------
__global__ void c2r_token_k(const float2* __restrict__ in, float* __restrict__ out)
{
    __shared__ float2 xc[HT];
    __shared__ float2 tw[29 * 56];
    for (int i = threadIdx.x; i < 29 * 56; i += 256) {
        int k = i / 56, x = i % 56;
        int m = (k * x) % 56;
        float c, s; sincospif(2.f * (float)m / 56.f, &s, &c);
        float mult = (k == 0 || k == 28) ? 1.f : 2.f;
        tw[i] = make_float2(mult * c, -mult * s);
    }
    long base = ((long)blockIdx.y * 256 + blockIdx.x) * HT;
    for (int i = threadIdx.x; i < HT; i += 256) xc[i] = in[base + i];
    __syncthreads();
    long ob = ((long)blockIdx.y * 256 + blockIdx.x) * NP;
    const float sc = 1.0f / 3136.0f;
    for (int o = threadIdx.x; o < NP; o += 256) {
        int r = o / 56, x = o % 56;
        float acc = 0.f;
#pragma unroll
        for (int k = 0; k < 29; k++) {
            float2 w = tw[k * 56 + x];
            float2 v = xc[r * 32 + k];
            acc = fmaf(v.x, w.x, fmaf(v.y, w.y, acc));
        }
        out[ob + o] += sc * acc;
    }
}

__global__ void cmulh_k(float2* __restrict__ a, const float2* __restrict__ b, long n)
{
    long i = (long)blockIdx.x * blockDim.x + threadIdx.x;
    if (i < n) {
        float2 av = a[i], bv = b[i];
        a[i] = make_float2(av.x * bv.x - av.y * bv.y, av.x * bv.y + av.y * bv.x);
    }
}

__global__ void twmulh_k(float2* __restrict__ f, const float* __restrict__ cw)
{
    int c = blockIdx.x, b = blockIdx.y;
    long base = ((long)b * 256 + c) * HT;
    for (int o = threadIdx.x; o < HT; o += 256) {
        int kx = o & 31;
        if (kx >= 29) continue;
        int ky = o >> 5;
        long wb = (((long)c * 56 + ky) * 29 + kx) * 2;
        float wr = cw[wb], wi = cw[wb + 1];
        float2 v = f[base + o];
        f[base + o] = make_float2(v.x * wr - v.y * wi, v.x * wi + v.y * wr);
    }
}

// ---------------- bf16 conversion kernels ----------------
__global__ void cvtqk_k(const float* __restrict__ src, long bstride,
                        __nv_bfloat162* __restrict__ dst, float scale)
{
    long i = (long)blockIdx.x * blockDim.x + threadIdx.x;
    if (i >= (long)Bb * 8 * NP * 16) return;
    int p = (int)(i & 15);
    long t = i >> 4;
    int n = (int)(t % NP);
    long t2 = t / NP;
    int h = (int)(t2 & 7), b = (int)(t2 >> 3);
    long s0 = (long)b * bstride + (long)(h * 32 + 2 * p) * NP + n;
    dst[i] = __floats2bfloat162_rn(src[s0] * scale, src[s0 + NP] * scale);
}

__global__ void cvtv_k(const float* __restrict__ tkv, __nv_bfloat162* __restrict__ dst)
{
    long i = (long)blockIdx.x * blockDim.x + threadIdx.x;
    if (i >= (long)Bb * 256 * NPH) return;
    int n2 = (int)(i % NPH);
    long cr = i / NPH;
    int b = (int)(cr >> 8), c = (int)(cr & 255);
    long s = (long)b * C2N + CN + (long)c * NP + 2 * n2;
    dst[i] = __floats2bfloat162_rn(tkv[s], tkv[s + 1]);
}

// ---------------- tensor-core flash attention ----------------
__device__ __forceinline__ void mma16816(float* c, const uint32_t* a, const uint32_t* b)
{
    asm volatile("mma.sync.aligned.m16n8k16.row.col.f32.bf16.bf16.f32 "
                 "{%0,%1,%2,%3}, {%4,%5,%6,%7}, {%8,%9}, {%0,%1,%2,%3};"
                 : "+f"(c[0]), "+f"(c[1]), "+f"(c[2]), "+f"(c[3])
                 : "r"(a[0]), "r"(a[1]), "r"(a[2]), "r"(a[3]), "r"(b[0]), "r"(b[1]));
}

__device__ __forceinline__ uint32_t packbf(float lo, float hi)
{
    __nv_bfloat162 h = __floats2bfloat162_rn(lo, hi);
    return *(uint32_t*)&h;
}

__global__ void flash_mma_k(const __nv_bfloat162* __restrict__ Qb,
                            const __nv_bfloat162* __restrict__ Kb,
                            const __nv_bfloat162* __restrict__ Vb,
                            float* __restrict__ O)
{
    int b = blockIdx.z, h = blockIdx.y;
    int warp = threadIdx.x >> 5, lane = threadIdx.x & 31;
    int g = lane >> 2, j = lane & 3;
    int q0 = blockIdx.x * 128 + warp * 16;
    if (q0 >= NP) return;
    const uint32_t* Qh = (const uint32_t*)(Qb + (long)(b * 8 + h) * NP * 16);
    const uint32_t* Kh = (const uint32_t*)(Kb + (long)(b * 8 + h) * NP * 16);
    const uint32_t* Vh = (const uint32_t*)(Vb + (long)(b * 256 + h * 32) * NPH);

    uint32_t qa[2][4];
#pragma unroll
    for (int kc = 0; kc < 2; kc++) {
        qa[kc][0] = Qh[(q0 + g)     * 16 + kc * 8 + j];
        qa[kc][1] = Qh[(q0 + g + 8) * 16 + kc * 8 + j];
        qa[kc][2] = Qh[(q0 + g)     * 16 + kc * 8 + j + 4];
        qa[kc][3] = Qh[(q0 + g + 8) * 16 + kc * 8 + j + 4];
    }

    float o_[4][4];
#pragma unroll
    for (int d = 0; d < 4; d++)
#pragma unroll
        for (int r = 0; r < 4; r++) o_[d][r] = 0.f;
    float mlo = -1e30f, mhi = -1e30f, llo = 0.f, lhi = 0.f;

#pragma unroll 1
    for (int kt = 0; kt < 196; kt++) {
        int kb = kt * 16;
        uint32_t kf[2][2][2];
#pragma unroll
        for (int nc = 0; nc < 2; nc++) {
            int key = kb + nc * 8 + g;
#pragma unroll
            for (int kc = 0; kc < 2; kc++) {
                kf[nc][kc][0] = Kh[key * 16 + kc * 8 + j];
                kf[nc][kc][1] = Kh[key * 16 + kc * 8 + j + 4];
            }
        }
        float s0[4] = {0.f, 0.f, 0.f, 0.f}, s1[4] = {0.f, 0.f, 0.f, 0.f};
        mma16816(s0, qa[0], kf[0][0]); mma16816(s0, qa[1], kf[0][1]);
        mma16816(s1, qa[0], kf[1][0]); mma16816(s1, qa[1], kf[1][1]);

        float tlo = fmaxf(fmaxf(s0[0], s0[1]), fmaxf(s1[0], s1[1]));
        float thi = fmaxf(fmaxf(s0[2], s0[3]), fmaxf(s1[2], s1[3]));
        tlo = fmaxf(tlo, __shfl_xor_sync(0xffffffff, tlo, 1));
        tlo = fmaxf(tlo, __shfl_xor_sync(0xffffffff, tlo, 2));
        thi = fmaxf(thi, __shfl_xor_sync(0xffffffff, thi, 1));
        thi = fmaxf(thi, __shfl_xor_sync(0xffffffff, thi, 2));
        float mnlo = fmaxf(mlo, tlo), mnhi = fmaxf(mhi, thi);
        float clo = __expf(mlo - mnlo), chi = __expf(mhi - mnhi);

        float p00 = __expf(s0[0] - mnlo), p01 = __expf(s0[1] - mnlo);
        float p02 = __expf(s0[2] - mnhi), p03 = __expf(s0[3] - mnhi);
        float p10 = __expf(s1[0] - mnlo), p11 = __expf(s1[1] - mnlo);
        float p12 = __expf(s1[2] - mnhi), p13 = __expf(s1[3] - mnhi);

        float sumlo = p00 + p01 + p10 + p11;
        float sumhi = p02 + p03 + p12 + p13;
        sumlo += __shfl_xor_sync(0xffffffff, sumlo, 1);
        sumlo += __shfl_xor_sync(0xffffffff, sumlo, 2);
        sumhi += __shfl_xor_sync(0xffffffff, sumhi, 1);
        sumhi += __shfl_xor_sync(0xffffffff, sumhi, 2);
        llo = llo * clo + sumlo;
        lhi = lhi * chi + sumhi;
#pragma unroll
        for (int d = 0; d < 4; d++) {
            o_[d][0] *= clo; o_[d][1] *= clo;
            o_[d][2] *= chi; o_[d][3] *= chi;
        }
        mlo = mnlo; mhi = mnhi;

        uint32_t pa[4];
        pa[0] = packbf(p00, p01);
        pa[1] = packbf(p02, p03);
        pa[2] = packbf(p10, p11);
        pa[3] = packbf(p12, p13);

#pragma unroll
        for (int dc = 0; dc < 4; dc++) {
            uint32_t vf[2];
            long vrow = (long)(dc * 8 + g) * NPH + (kb >> 1) + j;
            vf[0] = Vh[vrow];
            vf[1] = Vh[vrow + 4];
            mma16816(o_[dc], pa, vf);
        }
    }

    float invlo = 1.f / llo, invhi = 1.f / lhi;
#pragma unroll
    for (int dc = 0; dc < 4; dc++) {
        long d0 = (long)(b * 256 + h * 32 + dc * 8 + 2 * j) * NP;
        O[d0 + q0 + g]            = o_[dc][0] * invlo;
        O[d0 + NP + q0 + g]       = o_[dc][1] * invlo;
        O[d0 + q0 + g + 8]        = o_[dc][2] * invhi;
        O[d0 + NP + q0 + g + 8]   = o_[dc][3] * invhi;
    }
}

// ---------------- fuse ----------------
__global__ void gate_k(const float* __restrict__ hraw, const float* __restrict__ gam,
                       const float* __restrict__ bet, const float* __restrict__ w2,
                       const float* __restrict__ b2p, float* __restrict__ gate)
{
    int b = blockIdx.y;
    int n = blockIdx.x * 128 + threadIdx.x;
    if (n >= NP) return;
    const float inv = rsqrtf(1.f + 1e-5f);
    const float* hb = hraw + (long)b * CN + n;
    float g = b2p[0];
#pragma unroll 8
    for (int c = 0; c < 256; c++) {
        float hv = hb[(long)c * NP] * inv * gam[c] + bet[c];
        g = fmaf(w2[c], fmaxf(hv, 0.f), g);
    }
    gate[(long)b * NP + n] = 1.f / (1.f + __expf(-g));
}

__global__ void blend_k(const float* __restrict__ fuse, const float* __restrict__ gate,
                        float* __restrict__ out)
{
    long i = (long)blockIdx.x * blockDim.x + threadIdx.x;
    if (i >= TOT) return;
    long b = i / CN;
    long n = i % NP;
    float g = gate[b * NP + n];
    long fidx = i + b * CN;
    out[i] = g * fuse[fidx] + (1.f - g) * fuse[fidx + CN];
}

extern "C" void kernel_launch(void* const* d_in, const int* in_sizes, int n_in,
                              void* d_out, int out_size)
{
    const float* x        = (const float*)d_in[0];
    const float* ctx      = (const float*)d_in[1];
    const float* s_q_w    = (const float*)d_in[2];
    const float* s_kv_w   = (const float*)d_in[3];
    const float* s_proj_w = (const float*)d_in[4];
    const float* s_proj_b = (const float*)d_in[5];
    const float* s_dw_w   = (const float*)d_in[6];
    const float* s_dw_b   = (const float*)d_in[7];
    const float* t_q_w    = (const float*)d_in[8];
    const float* t_kv_w   = (const float*)d_in[9];
    const float* t_proj_w = (const float*)d_in[10];
    const float* t_proj_b = (const float*)d_in[11];
    const float* t_cw     = (const float*)d_in[12];
    const float* g_w1     = (const float*)d_in[13];
    const float* g_bn_g   = (const float*)d_in[14];
    const float* g_bn_b   = (const float*)d_in[15];
    const float* g_w2     = (const float*)d_in[16];
    const float* g_b2     = (const float*)d_in[17];
    float* out = (float*)d_out;

    float *sq, *skv, *tq, *tkv, *vloc, *spre, *xat, *fuse, *hbuf, *gate;
    float2 *sp1, *sp2, *sp3;
    __nv_bfloat162 *qb, *kb, *vb;
    cudaGetSymbolAddress((void**)&sq,   g_sq);
    cudaGetSymbolAddress((void**)&skv,  g_skv);
    cudaGetSymbolAddress((void**)&tq,   g_tq);
    cudaGetSymbolAddress((void**)&tkv,  g_tkv);
    cudaGetSymbolAddress((void**)&vloc, g_vloc);
    cudaGetSymbolAddress((void**)&spre, g_spre);
    cudaGetSymbolAddress((void**)&xat,  g_xat);
    cudaGetSymbolAddress((void**)&fuse, g_fusb);
    cudaGetSymbolAddress((void**)&hbuf, g_hbuf);
    cudaGetSymbolAddress((void**)&gate, g_gate);
    cudaGetSymbolAddress((void**)&sp1,  g_sp1);
    cudaGetSymbolAddress((void**)&sp2,  g_sp2);
    cudaGetSymbolAddress((void**)&sp3,  g_sp3);
    cudaGetSymbolAddress((void**)&qb,   g_qb);
    cudaGetSymbolAddress((void**)&kb,   g_kb);
    cudaGetSymbolAddress((void**)&vb,   g_vb);

    const float SCALE = 0.17677669529663687f;
    dim3 blk256(256), blk128(128);
    dim3 gC(256, Bb);
    dim3 gT2(49, 2, Bb);        // tf32 gemm O=256 (128-row tiles)
    dim3 gT4(49, 4, Bb);        // tf32 gemm O=512
    long nHalf = (long)Bb * CHT;

    // ---- spectral branch ----
    gemm_tf32_k<<<gT2, blk256>>>(s_q_w, x, sq, nullptr, 256, CN, CN);
    gemm_tf32_k<<<gT4, blk256>>>(s_kv_w, ctx, skv, nullptr, 256, CN, C2N);
    dwconv_k<<<gC, blk256>>>(skv, s_dw_w, s_dw_b, vloc);
    r2cw_k<<<gC, blk256>>>(sq, CN, sp1);
    c2ch_k<<<gC, blk256>>>(sp1, sp2, 1.f);
    r2cw_k<<<gC, blk256>>>(skv, C2N, sp1);            // k half
    c2ch_k<<<gC, blk256>>>(sp1, sp3, 1.f);
    cmulh_k<<<dim3((unsigned)((nHalf + 255) / 256)), blk256>>>(sp2, sp3, nHalf);
    c2ch_k<<<gC, blk256>>>(sp2, sp1, -1.f);
    c2r_spec_k<<<gC, blk256>>>(sp1, skv, vloc, spre);
    gemm_tf32_k<<<gT2, blk256>>>(s_proj_w, spre, fuse, s_proj_b, 256, CN, C2N);

    // ---- token branch ----
    gemm_tf32_k<<<gT2, blk256>>>(t_q_w, x, tq, nullptr, 256, CN, CN);
    gemm_tf32_k<<<gT4, blk256>>>(t_kv_w, ctx, tkv, nullptr, 256, CN, C2N);
    cvtqk_k<<<dim3(3136), blk256>>>(tq, CN, qb, SCALE);
    cvtqk_k<<<dim3(3136), blk256>>>(tkv, C2N, kb, 1.f);
    cvtv_k<<<dim3(3136), blk256>>>(tkv, vb);
    flash_mma_k<<<dim3(25, 8, Bb), blk256>>>(qb, kb, vb, xat);
    r2cw_k<<<gC, blk256>>>(tkv + CN, C2N, sp1);       // v_img
    c2ch_k<<<gC, blk256>>>(sp1, sp2, 1.f);
    twmulh_k<<<gC, blk256>>>(sp2, t_cw);
    c2ch_k<<<gC, blk256>>>(sp2, sp1, -1.f);
    c2r_token_k<<<gC, blk256>>>(sp1, xat);            // += into x_attn
    gemm_tf32_k<<<gT2, blk256>>>(t_proj_w, xat, fuse + CN, t_proj_b, 256, CN, C2N);

    // ---- fuse ----
    gemm_tf32_k<<<gT2, blk256>>>(g_w1, fuse, hbuf, nullptr, 512, C2N, CN);
    gate_k<<<dim3(25, Bb), blk128>>>(hbuf, g_bn_g, g_bn_b, g_w2, g_b2, gate);
    blend_k<<<dim3((unsigned)((TOT + 255) / 256)), blk256>>>(fuse, gate, out);
}

// round 10
// speedup vs baseline: 2.5753x; 1.0623x over previous
#include <cuda_runtime.h>
#include <cuda_bf16.h>
#include <stdint.h>
#include <math.h>

#define NP 3136
#define Bb 2
#define CN 802816L
#define C2N 1605632L
#define TOT 1605632L
#define HT 1792            // 56*32 padded half-spectrum elems per image
#define NPH 1568           // NP/2 (bf16 pairs per row)

// ---------------- scratch ----------------
static __device__ float g_sq  [TOT];
static __device__ float g_skv [Bb*C2N];
static __device__ float g_tq  [TOT];
static __device__ float g_tkv [Bb*C2N];
static __device__ float g_spre[TOT];
static __device__ float g_xat [TOT];
static __device__ float g_fusb[Bb*C2N];
static __device__ float g_hbuf[TOT];
static __device__ float g_gate[Bb*NP];
static __device__ __nv_bfloat162 g_qb[Bb*8L*NP*16];   // [b][h][n][d/2]
static __device__ __nv_bfloat162 g_kb[Bb*8L*NP*16];
static __device__ __nv_bfloat162 g_vb[Bb*256L*NPH];   // [b][c][n/2]

// ---------------- TF32 tensor-core GEMM ----------------
__device__ __forceinline__ float tf32r(float x)
{
    uint32_t u;
    asm("cvt.rna.tf32.f32 %0, %1;" : "=r"(u) : "f"(x));
    return __uint_as_float(u);
}

__device__ __forceinline__ void mma_tf32(float* c, const uint32_t* a, const uint32_t* b)
{
    asm volatile("mma.sync.aligned.m16n8k8.row.col.f32.tf32.tf32.f32 "
                 "{%0,%1,%2,%3}, {%4,%5,%6,%7}, {%8,%9}, {%0,%1,%2,%3};"
                 : "+f"(c[0]), "+f"(c[1]), "+f"(c[2]), "+f"(c[3])
                 : "r"(a[0]), "r"(a[1]), "r"(a[2]), "r"(a[3]), "r"(b[0]), "r"(b[1]));
}

__global__ void gemm_tf32_k(const float* __restrict__ W, const float* __restrict__ X,
                            float* __restrict__ Y, const float* __restrict__ bias,
                            int I, long xB, long yB)
{
    __shared__ float Ws[128][20];
    __shared__ float Xs[16][65];
    int tid = threadIdx.x;
    int warp = tid >> 5, lane = tid & 31;
    int g = lane >> 2, j = lane & 3;
    int warp_o = warp & 3, warp_n = warp >> 2;
    int nb = blockIdx.x * 64, ob = blockIdx.y * 128;
    const float* Xb = X + (long)blockIdx.z * xB;
    float*       Yb = Y + (long)blockIdx.z * yB;

    float acc[2][4][4];
#pragma unroll
    for (int mo = 0; mo < 2; mo++)
#pragma unroll
        for (int nn = 0; nn < 4; nn++)
#pragma unroll
            for (int r = 0; r < 4; r++) acc[mo][nn][r] = 0.f;

    int wrow = tid >> 1, whf = (tid & 1) * 8;
    int xrow = tid >> 4, xc4 = (tid & 15) * 4;

    for (int kt = 0; kt < I; kt += 16) {
        float4 w0 = *(const float4*)&W[(long)(ob + wrow) * I + kt + whf];
        float4 w1 = *(const float4*)&W[(long)(ob + wrow) * I + kt + whf + 4];
        Ws[wrow][whf + 0] = tf32r(w0.x); Ws[wrow][whf + 1] = tf32r(w0.y);
        Ws[wrow][whf + 2] = tf32r(w0.z); Ws[wrow][whf + 3] = tf32r(w0.w);
        Ws[wrow][whf + 4] = tf32r(w1.x); Ws[wrow][whf + 5] = tf32r(w1.y);
        Ws[wrow][whf + 6] = tf32r(w1.z); Ws[wrow][whf + 7] = tf32r(w1.w);
        float4 xv = *(const float4*)&Xb[(long)(kt + xrow) * NP + nb + xc4];
        Xs[xrow][xc4 + 0] = tf32r(xv.x); Xs[xrow][xc4 + 1] = tf32r(xv.y);
        Xs[xrow][xc4 + 2] = tf32r(xv.z); Xs[xrow][xc4 + 3] = tf32r(xv.w);
        __syncthreads();
#pragma unroll
        for (int kk = 0; kk < 16; kk += 8) {
            uint32_t a[2][4], b[4][2];
#pragma unroll
            for (int mo = 0; mo < 2; mo++) {
                int r0 = warp_o * 32 + mo * 16 + g;
                a[mo][0] = __float_as_uint(Ws[r0][kk + j]);
                a[mo][1] = __float_as_uint(Ws[r0 + 8][kk + j]);
                a[mo][2] = __float_as_uint(Ws[r0][kk + j + 4]);
                a[mo][3] = __float_as_uint(Ws[r0 + 8][kk + j + 4]);
            }
#pragma unroll
            for (int nn = 0; nn < 4; nn++) {
                int cc = warp_n * 32 + nn * 8 + g;
                b[nn][0] = __float_as_uint(Xs[kk + j][cc]);
                b[nn][1] = __float_as_uint(Xs[kk + j + 4][cc]);
            }
#pragma unroll
            for (int mo = 0; mo < 2; mo++)
#pragma unroll
                for (int nn = 0; nn < 4; nn++)
                    mma_tf32(acc[mo][nn], a[mo], b[nn]);
        }
        __syncthreads();
    }

#pragma unroll
    for (int mo = 0; mo < 2; mo++) {
        int r0 = ob + warp_o * 32 + mo * 16 + g;
        float bs0 = bias ? bias[r0] : 0.f;
        float bs1 = bias ? bias[r0 + 8] : 0.f;
#pragma unroll
        for (int nn = 0; nn < 4; nn++) {
            int col = nb + warp_n * 32 + nn * 8 + j * 2;
            float2 v0 = make_float2(acc[mo][nn][0] + bs0, acc[mo][nn][1] + bs0);
            float2 v1 = make_float2(acc[mo][nn][2] + bs1, acc[mo][nn][3] + bs1);
            *(float2*)&Yb[(long)r0 * NP + col] = v0;
            *(float2*)&Yb[(long)(r0 + 8) * NP + col] = v1;
        }
    }
}

// ---------------- fused DFT helpers ----------------
__device__ __forceinline__ void load_tables(float2* T1, float2* T2, float2* T3, int tid)
{
    for (int i = tid; i < HT; i += 256) {
        int n = i >> 5, k = i & 31;
        float c = 0.f, s = 0.f;
        if (k < 29) { int m = (n * k) % 56; sincospif(2.f * (float)m / 56.f, &s, &c); }
        T1[i] = make_float2(c, s);
    }
    for (int i = tid; i < NP; i += 256) {
        int r = i / 56, kh = i % 56;
        int m = (r * kh) % 56;
        float c, s; sincospif(2.f * (float)m / 56.f, &s, &c);
        T2[i] = make_float2(c, s);
    }
    for (int i = tid; i < 29 * 56; i += 256) {
        int k = i / 56, x = i % 56;
        int m = (k * x) % 56;
        float c, s; sincospif(2.f * (float)m / 56.f, &s, &c);
        float mult = (k == 0 || k == 28) ? 1.f : 2.f;
        T3[i] = make_float2(mult * c, -mult * s);
    }
}

// out[r][k] = sum_n img[r][n] e^{-2pi i k n / 56}
__device__ __forceinline__ void r2cw_stage(const float* img, const float2* T1,
                                           float2* out, int tid)
{
    for (int o = tid; o < HT; o += 256) {
        int r = o >> 5, k = o & 31;
        if (k >= 29) continue;
        const float* xr = img + r * 56;
        float ac = 0.f, as = 0.f;
#pragma unroll 14
        for (int n = 0; n < 56; n++) {
            float2 w = T1[n * 32 + k];
            float v = xr[n];
            ac = fmaf(v, w.x, ac);
            as = fmaf(v, w.y, as);
        }
        out[o] = make_float2(ac, -as);
    }
}

// fwd: pr = vx*c + vy*s, pi = vy*c - vx*s;  inv: flip s sign
template<int SG>
__device__ __forceinline__ void c2ch_stage(const float2* in, const float2* T2,
                                           float2* out, int tid)
{
    for (int o = tid; o < HT; o += 256) {
        int kh = o >> 5, kx = o & 31;
        if (kx >= 29) continue;
        float pr = 0.f, pi = 0.f;
#pragma unroll 14
        for (int r = 0; r < 56; r++) {
            float2 w = T2[r * 56 + kh];
            float2 v = in[r * 32 + kx];
            if (SG > 0) {
                pr = fmaf(v.x, w.x, fmaf(v.y, w.y, pr));
                pi = fmaf(v.y, w.x, fmaf(-v.x, w.y, pi));
            } else {
                pr = fmaf(v.x, w.x, fmaf(-v.y, w.y, pr));
                pi = fmaf(v.y, w.x, fmaf(v.x, w.y, pi));
            }
        }
        out[o] = make_float2(pr, pi);
    }
}

// ---------------- fused spectral branch (whole DFT chain + dwconv epilogue) ----------
// grid (256, Bb), block 256; dynamic smem
extern "C" __global__ void spec_fused_k(const float* __restrict__ sq,
                                        const float* __restrict__ skv,
                                        const float* __restrict__ dww,
                                        const float* __restrict__ dwb,
                                        float* __restrict__ out)
{
    extern __shared__ float sm[];
    float*  img = sm;                         // 3136
    float2* A   = (float2*)(sm + NP);         // 1792
    float2* Bf  = A + HT;
    float2* Cf  = Bf + HT;
    float2* T1  = Cf + HT;
    float2* T2  = T1 + HT;
    float2* T3  = T2 + NP;
    int tid = threadIdx.x;
    int c = blockIdx.x, b = blockIdx.y;

    load_tables(T1, T2, T3, tid);
    const float* qp = sq  + ((long)b * 256 + c) * NP;
    const float* kp = skv + ((long)b * 512 + c) * NP;
    const float* vp = skv + ((long)b * 512 + 256 + c) * NP;

    for (int i = tid; i < NP; i += 256) img[i] = qp[i];
    __syncthreads();
    r2cw_stage(img, T1, A, tid);
    __syncthreads();
    c2ch_stage<1>(A, T2, Cf, tid);            // Cf = Fq
    for (int i = tid; i < NP; i += 256) img[i] = kp[i];
    __syncthreads();
    r2cw_stage(img, T1, A, tid);
    __syncthreads();
    c2ch_stage<1>(A, T2, Bf, tid);            // Bf = Fk
    __syncthreads();
    for (int o = tid; o < HT; o += 256) {     // A = Fq * Fk
        if ((o & 31) >= 29) continue;
        float2 a = Cf[o], bb = Bf[o];
        A[o] = make_float2(a.x * bb.x - a.y * bb.y, a.x * bb.y + a.y * bb.x);
    }
    __syncthreads();
    c2ch_stage<-1>(A, T2, Bf, tid);           // inverse along H
    for (int i = tid; i < NP; i += 256) img[i] = vp[i];   // v for epilogue
    __syncthreads();

    float wr[9];
#pragma unroll
    for (int i = 0; i < 9; i++) wr[i] = dww[c * 9 + i];
    float bsv = dwb[c];
    long ob = ((long)b * 256 + c) * NP;
    const float sc = 1.0f / 175616.0f;        // 1/N^{3/2}
    for (int o = tid; o < NP; o += 256) {
        int y = o / 56, x = o % 56;
        float acc = 0.f;
#pragma unroll
        for (int k = 0; k < 29; k++) {
            float2 w = T3[k * 56 + x];
            float2 v = Bf[y * 32 + k];
            acc = fmaf(v.x, w.x, fmaf(v.y, w.y, acc));
        }
        float dv = bsv;                       // depthwise 3x3 on v (in smem)
#pragma unroll
        for (int dy = -1; dy <= 1; dy++) {
            int yy = y + dy;
            if ((unsigned)yy >= 56u) continue;
#pragma unroll
            for (int dx = -1; dx <= 1; dx++) {
                int xx = x + dx;
                if ((unsigned)xx >= 56u) continue;
                dv += wr[(dy + 1) * 3 + dx + 1] * img[yy * 56 + xx];
            }
        }
        out[ob + o] = (sc * acc) * img[o] + dv;
    }
}

// ---------------- fused token spectral-residual (whole DFT chain) ----------
extern "C" __global__ void token_fused_k(const float* __restrict__ tkv,
                                         const float* __restrict__ cw,
                                         float* __restrict__ xat)
{
    extern __shared__ float sm[];
    float*  img = sm;
    float2* A   = (float2*)(sm + NP);
    float2* Bf  = A + HT;
    float2* T1  = Bf + HT;
    float2* T2  = T1 + HT;
    float2* T3  = T2 + NP;
    int tid = threadIdx.x;
    int c = blockIdx.x, b = blockIdx.y;

    load_tables(T1, T2, T3, tid);
    const float* vp = tkv + (long)b * C2N + CN + (long)c * NP;
    for (int i = tid; i < NP; i += 256) img[i] = vp[i];
    __syncthreads();
    r2cw_stage(img, T1, A, tid);
    __syncthreads();
    c2ch_stage<1>(A, T2, Bf, tid);
    __syncthreads();
    for (int o = tid; o < HT; o += 256) {     // multiply by complex weight
        int kx = o & 31;
        if (kx >= 29) continue;
        int ky = o >> 5;
        long wb = (((long)c * 56 + ky) * 29 + kx) * 2;
        float wrr = cw[wb], wii = cw[wb + 1];
        float2 v = Bf[o];
        Bf[o] = make_float2(v.x * wrr - v.y * wii, v.x * wii + v.y * wrr);
    }
    __syncthreads();
    c2ch_stage<-1>(Bf, T2, A, tid);
    __syncthreads();
    long ob = ((long)b * 256 + c) * NP;
    const float sc = 1.0f / 3136.0f;
    for (int o = tid; o < NP; o += 256) {
        int y = o / 56, x = o % 56;
        float acc = 0.f;
#pragma unroll
        for (int k = 0; k < 29; k++) {
            float2 w = T3[k * 56 + x];
            float2 v = A[y * 32 + k];
            acc = fmaf(v.x, w.x, fmaf(v.y, w.y, acc));
        }
        xat[ob + o] += sc * acc;
    }
}

// ---------------- bf16 conversion kernels ----------------
__global__ void cvtqk_k(const float* __restrict__ src, long bstride,
                        __nv_bfloat162* __restrict__ dst, float scale)
{
    long i = (long)blockIdx.x * blockDim.x + threadIdx.x;
    if (i >= (long)Bb * 8 * NP * 16) return;
    int p = (int)(i & 15);
    long t = i >> 4;
    int n = (int)(t % NP);
    long t2 = t / NP;
    int h = (int)(t2 & 7), b = (int)(t2 >> 3);
    long s0 = (long)b * bstride + (long)(h * 32 + 2 * p) * NP + n;
    dst[i] = __floats2bfloat162_rn(src[s0] * scale, src[s0 + NP] * scale);
}

__global__ void cvtv_k(const float* __restrict__ tkv, __nv_bfloat162* __restrict__ dst)
{
    long i = (long)blockIdx.x * blockDim.x + threadIdx.x;
    if (i >= (long)Bb * 256 * NPH) return;
    int n2 = (int)(i % NPH);
    long cr = i / NPH;
    int b = (int)(cr >> 8), c = (int)(cr & 255);
    long s = (long)b * C2N + CN + (long)c * NP + 2 * n2;
    dst[i] = __floats2bfloat162_rn(tkv[s], tkv[s + 1]);
}

// ---------------- tensor-core flash attention ----------------
__device__ __forceinline__ void mma16816(float* c, const uint32_t* a, const uint32_t* b)
{
    asm volatile("mma.sync.aligned.m16n8k16.row.col.f32.bf16.bf16.f32 "
                 "{%0,%1,%2,%3}, {%4,%5,%6,%7}, {%8,%9}, {%0,%1,%2,%3};"
                 : "+f"(c[0]), "+f"(c[1]), "+f"(c[2]), "+f"(c[3])
                 : "r"(a[0]), "r"(a[1]), "r"(a[2]), "r"(a[3]), "r"(b[0]), "r"(b[1]));
}

__device__ __forceinline__ uint32_t packbf(float lo, float hi)
{
    __nv_bfloat162 h = __floats2bfloat162_rn(lo, hi);
    return *(uint32_t*)&h;
}

__global__ void flash_mma_k(const __nv_bfloat162* __restrict__ Qb,
                            const __nv_bfloat162* __restrict__ Kb,
                            const __nv_bfloat162* __restrict__ Vb,
                            float* __restrict__ O)
{
    int b = blockIdx.z, h = blockIdx.y;
    int warp = threadIdx.x >> 5, lane = threadIdx.x & 31;
    int g = lane >> 2, j = lane & 3;
    int q0 = blockIdx.x * 128 + warp * 16;
    if (q0 >= NP) return;
    const uint32_t* Qh = (const uint32_t*)(Qb + (long)(b * 8 + h) * NP * 16);
    const uint32_t* Kh = (const uint32_t*)(Kb + (long)(b * 8 + h) * NP * 16);
    const uint32_t* Vh = (const uint32_t*)(Vb + (long)(b * 256 + h * 32) * NPH);

    uint32_t qa[2][4];
#pragma unroll
    for (int kc = 0; kc < 2; kc++) {
        qa[kc][0] = Qh[(q0 + g)     * 16 + kc * 8 + j];
        qa[kc][1] = Qh[(q0 + g + 8) * 16 + kc * 8 + j];
        qa[kc][2] = Qh[(q0 + g)     * 16 + kc * 8 + j + 4];
        qa[kc][3] = Qh[(q0 + g + 8) * 16 + kc * 8 + j + 4];
    }

    float o_[4][4];
#pragma unroll
    for (int d = 0; d < 4; d++)
#pragma unroll
        for (int r = 0; r < 4; r++) o_[d][r] = 0.f;
    float mlo = -1e30f, mhi = -1e30f, llo = 0.f, lhi = 0.f;

#pragma unroll 1
    for (int kt = 0; kt < 196; kt++) {
        int kb = kt * 16;
        uint32_t kf[2][2][2];
#pragma unroll
        for (int nc = 0; nc < 2; nc++) {
            int key = kb + nc * 8 + g;
#pragma unroll
            for (int kc = 0; kc < 2; kc++) {
                kf[nc][kc][0] = Kh[key * 16 + kc * 8 + j];
                kf[nc][kc][1] = Kh[key * 16 + kc * 8 + j + 4];
            }
        }
        float s0[4] = {0.f, 0.f, 0.f, 0.f}, s1[4] = {0.f, 0.f, 0.f, 0.f};
        mma16816(s0, qa[0], kf[0][0]); mma16816(s0, qa[1], kf[0][1]);
        mma16816(s1, qa[0], kf[1][0]); mma16816(s1, qa[1], kf[1][1]);

        float tlo = fmaxf(fmaxf(s0[0], s0[1]), fmaxf(s1[0], s1[1]));
        float thi = fmaxf(fmaxf(s0[2], s0[3]), fmaxf(s1[2], s1[3]));
        tlo = fmaxf(tlo, __shfl_xor_sync(0xffffffff, tlo, 1));
        tlo = fmaxf(tlo, __shfl_xor_sync(0xffffffff, tlo, 2));
        thi = fmaxf(thi, __shfl_xor_sync(0xffffffff, thi, 1));
        thi = fmaxf(thi, __shfl_xor_sync(0xffffffff, thi, 2));
        float mnlo = fmaxf(mlo, tlo), mnhi = fmaxf(mhi, thi);
        float clo = __expf(mlo - mnlo), chi = __expf(mhi - mnhi);

        float p00 = __expf(s0[0] - mnlo), p01 = __expf(s0[1] - mnlo);
        float p02 = __expf(s0[2] - mnhi), p03 = __expf(s0[3] - mnhi);
        float p10 = __expf(s1[0] - mnlo), p11 = __expf(s1[1] - mnlo);
        float p12 = __expf(s1[2] - mnhi), p13 = __expf(s1[3] - mnhi);

        float sumlo = p00 + p01 + p10 + p11;
        float sumhi = p02 + p03 + p12 + p13;
        sumlo += __shfl_xor_sync(0xffffffff, sumlo, 1);
        sumlo += __shfl_xor_sync(0xffffffff, sumlo, 2);
        sumhi += __shfl_xor_sync(0xffffffff, sumhi, 1);
        sumhi += __shfl_xor_sync(0xffffffff, sumhi, 2);
        llo = llo * clo + sumlo;
        lhi = lhi * chi + sumhi;
#pragma unroll
        for (int d = 0; d < 4; d++) {
            o_[d][0] *= clo; o_[d][1] *= clo;
            o_[d][2] *= chi; o_[d][3] *= chi;
        }
        mlo = mnlo; mhi = mnhi;

        uint32_t pa[4];
        pa[0] = packbf(p00, p01);
        pa[1] = packbf(p02, p03);
        pa[2] = packbf(p10, p11);
        pa[3] = packbf(p12, p13);

#pragma unroll
        for (int dc = 0; dc < 4; dc++) {
            uint32_t vf[2];
            long vrow = (long)(dc * 8 + g) * NPH + (kb >> 1) + j;
            vf[0] = Vh[vrow];
            vf[1] = Vh[vrow + 4];
            mma16816(o_[dc], pa, vf);
        }
    }

    float invlo = 1.f / llo, invhi = 1.f / lhi;
#pragma unroll
    for (int dc = 0; dc < 4; dc++) {
        long d0 = (long)(b * 256 + h * 32 + dc * 8 + 2 * j) * NP;
        O[d0 + q0 + g]            = o_[dc][0] * invlo;
        O[d0 + NP + q0 + g]       = o_[dc][1] * invlo;
        O[d0 + q0 + g + 8]        = o_[dc][2] * invhi;
        O[d0 + NP + q0 + g + 8]   = o_[dc][3] * invhi;
    }
}

// ---------------- fuse ----------------
__global__ void gate_k(const float* __restrict__ hraw, const float* __restrict__ gam,
                       const float* __restrict__ bet, const float* __restrict__ w2,
                       const float* __restrict__ b2p, float* __restrict__ gate)
{
    int b = blockIdx.y;
    int n = blockIdx.x * 128 + threadIdx.x;
    if (n >= NP) return;
    const float inv = rsqrtf(1.f + 1e-5f);
    const float* hb = hraw + (long)b * CN + n;
    float g = b2p[0];
#pragma unroll 8
    for (int c = 0; c < 256; c++) {
        float hv = hb[(long)c * NP] * inv * gam[c] + bet[c];
        g = fmaf(w2[c], fmaxf(hv, 0.f), g);
    }
    gate[(long)b * NP + n] = 1.f / (1.f + __expf(-g));
}

__global__ void blend_k(const float* __restrict__ fuse, const float* __restrict__ gate,
                        float* __restrict__ out)
{
    long i = (long)blockIdx.x * blockDim.x + threadIdx.x;
    if (i >= TOT) return;
    long b = i / CN;
    long n = i % NP;
    float g = gate[b * NP + n];
    long fidx = i + b * CN;
    out[i] = g * fuse[fidx] + (1.f - g) * fuse[fidx + CN];
}

extern "C" void kernel_launch(void* const* d_in, const int* in_sizes, int n_in,
                              void* d_out, int out_size)
{
    const float* x        = (const float*)d_in[0];
    const float* ctx      = (const float*)d_in[1];
    const float* s_q_w    = (const float*)d_in[2];
    const float* s_kv_w   = (const float*)d_in[3];
    const float* s_proj_w = (const float*)d_in[4];
    const float* s_proj_b = (const float*)d_in[5];
    const float* s_dw_w   = (const float*)d_in[6];
    const float* s_dw_b   = (const float*)d_in[7];
    const float* t_q_w    = (const float*)d_in[8];
    const float* t_kv_w   = (const float*)d_in[9];
    const float* t_proj_w = (const float*)d_in[10];
    const float* t_proj_b = (const float*)d_in[11];
    const float* t_cw     = (const float*)d_in[12];
    const float* g_w1     = (const float*)d_in[13];
    const float* g_bn_g   = (const float*)d_in[14];
    const float* g_bn_b   = (const float*)d_in[15];
    const float* g_w2     = (const float*)d_in[16];
    const float* g_b2     = (const float*)d_in[17];
    float* out = (float*)d_out;

    float *sq, *skv, *tq, *tkv, *spre, *xat, *fuse, *hbuf, *gate;
    __nv_bfloat162 *qb, *kb, *vb;
    cudaGetSymbolAddress((void**)&sq,   g_sq);
    cudaGetSymbolAddress((void**)&skv,  g_skv);
    cudaGetSymbolAddress((void**)&tq,   g_tq);
    cudaGetSymbolAddress((void**)&tkv,  g_tkv);
    cudaGetSymbolAddress((void**)&spre, g_spre);
    cudaGetSymbolAddress((void**)&xat,  g_xat);
    cudaGetSymbolAddress((void**)&fuse, g_fusb);
    cudaGetSymbolAddress((void**)&hbuf, g_hbuf);
    cudaGetSymbolAddress((void**)&gate, g_gate);
    cudaGetSymbolAddress((void**)&qb,   g_qb);
    cudaGetSymbolAddress((void**)&kb,   g_kb);
    cudaGetSymbolAddress((void**)&vb,   g_vb);

    // dynamic smem sizes (floats): img + float2 buffers/tables
    const int SPEC_SMEM  = (NP + 2 * (3 * HT + HT + NP + 29 * 56)) * 4;   // ~105 KB
    const int TOKEN_SMEM = (NP + 2 * (2 * HT + HT + NP + 29 * 56)) * 4;   // ~91 KB
    static int attr_done = 0;
    cudaFuncSetAttribute(spec_fused_k,  cudaFuncAttributeMaxDynamicSharedMemorySize, SPEC_SMEM);
    cudaFuncSetAttribute(token_fused_k, cudaFuncAttributeMaxDynamicSharedMemorySize, TOKEN_SMEM);
    (void)attr_done;

    const float SCALE = 0.17677669529663687f;
    dim3 blk256(256), blk128(128);
    dim3 gC(256, Bb);
    dim3 gT2(49, 2, Bb);
    dim3 gT4(49, 4, Bb);

    // ---- spectral branch ----
    gemm_tf32_k<<<gT2, blk256>>>(s_q_w, x, sq, nullptr, 256, CN, CN);
    gemm_tf32_k<<<gT4, blk256>>>(s_kv_w, ctx, skv, nullptr, 256, CN, C2N);
    spec_fused_k<<<gC, blk256, SPEC_SMEM>>>(sq, skv, s_dw_w, s_dw_b, spre);
    gemm_tf32_k<<<gT2, blk256>>>(s_proj_w, spre, fuse, s_proj_b, 256, CN, C2N);

    // ---- token branch ----
    gemm_tf32_k<<<gT2, blk256>>>(t_q_w, x, tq, nullptr, 256, CN, CN);
    gemm_tf32_k<<<gT4, blk256>>>(t_kv_w, ctx, tkv, nullptr, 256, CN, C2N);
    cvtqk_k<<<dim3(3136), blk256>>>(tq, CN, qb, SCALE);
    cvtqk_k<<<dim3(3136), blk256>>>(tkv, C2N, kb, 1.f);
    cvtv_k<<<dim3(3136), blk256>>>(tkv, vb);
    flash_mma_k<<<dim3(25, 8, Bb), blk256>>>(qb, kb, vb, xat);
    token_fused_k<<<gC, blk256, TOKEN_SMEM>>>(tkv, t_cw, xat);   // += into x_attn
    gemm_tf32_k<<<gT2, blk256>>>(t_proj_w, xat, fuse + CN, t_proj_b, 256, CN, C2N);

    // ---- fuse ----
    gemm_tf32_k<<<gT2, blk256>>>(g_w1, fuse, hbuf, nullptr, 512, C2N, CN);
    gate_k<<<dim3(25, Bb), blk128>>>(hbuf, g_bn_g, g_bn_b, g_w2, g_b2, gate);
    blend_k<<<dim3((unsigned)((TOT + 255) / 256)), blk256>>>(fuse, gate, out);
}

// round 13
// speedup vs baseline: 2.9188x; 1.1334x over previous
#include <cuda_runtime.h>
#include <cuda_bf16.h>
#include <stdint.h>
#include <math.h>

#define NP 3136
#define Bb 2
#define CN 802816L
#define C2N 1605632L
#define TOT 1605632L
#define HT 1792
#define NPH 1568

// ---------------- scratch ----------------
static __device__ float g_sq  [TOT];
static __device__ float g_skv [Bb*C2N];
static __device__ float g_tq  [TOT];
static __device__ float g_tkv [Bb*C2N];
static __device__ float g_spre[TOT];
static __device__ float g_xat [TOT];
static __device__ float g_fusb[Bb*C2N];
static __device__ float g_hbuf[TOT];
static __device__ float g_gate[Bb*NP];
static __device__ __nv_bfloat162 g_qb[Bb*8L*NP*16];
static __device__ __nv_bfloat162 g_kb[Bb*8L*NP*16];
static __device__ __nv_bfloat162 g_vb[Bb*256L*NPH];

// ---------------- TF32 GEMM core ----------------
__device__ __forceinline__ float tf32r(float x)
{
    uint32_t u;
    asm("cvt.rna.tf32.f32 %0, %1;" : "=r"(u) : "f"(x));
    return __uint_as_float(u);
}

__device__ __forceinline__ void mma_tf32(float* c, const uint32_t* a, const uint32_t* b)
{
    asm volatile("mma.sync.aligned.m16n8k8.row.col.f32.tf32.tf32.f32 "
                 "{%0,%1,%2,%3}, {%4,%5,%6,%7}, {%8,%9}, {%0,%1,%2,%3};"
                 : "+f"(c[0]), "+f"(c[1]), "+f"(c[2]), "+f"(c[3])
                 : "r"(a[0]), "r"(a[1]), "r"(a[2]), "r"(a[3]), "r"(b[0]), "r"(b[1]));
}

// W: row 0 = this block's first output row; X: batch base; Y: this block's first row base.
__device__ __forceinline__ void gemm_core(const float* __restrict__ W,
                                          const float* __restrict__ X,
                                          float* __restrict__ Y,
                                          const float* __restrict__ bias,
                                          int I, int nb,
                                          float (*Ws)[20], float (*Xs)[65])
{
    int tid = threadIdx.x;
    int warp = tid >> 5, lane = tid & 31;
    int g = lane >> 2, j = lane & 3;
    int warp_o = warp & 3, warp_n = warp >> 2;

    float acc[2][4][4];
#pragma unroll
    for (int mo = 0; mo < 2; mo++)
#pragma unroll
        for (int nn = 0; nn < 4; nn++)
#pragma unroll
            for (int r = 0; r < 4; r++) acc[mo][nn][r] = 0.f;

    int wrow = tid >> 1, whf = (tid & 1) * 8;
    int xrow = tid >> 4, xc4 = (tid & 15) * 4;

    for (int kt = 0; kt < I; kt += 16) {
        float4 w0 = *(const float4*)&W[(long)wrow * I + kt + whf];
        float4 w1 = *(const float4*)&W[(long)wrow * I + kt + whf + 4];
        Ws[wrow][whf + 0] = tf32r(w0.x); Ws[wrow][whf + 1] = tf32r(w0.y);
        Ws[wrow][whf + 2] = tf32r(w0.z); Ws[wrow][whf + 3] = tf32r(w0.w);
        Ws[wrow][whf + 4] = tf32r(w1.x); Ws[wrow][whf + 5] = tf32r(w1.y);
        Ws[wrow][whf + 6] = tf32r(w1.z); Ws[wrow][whf + 7] = tf32r(w1.w);
        float4 xv = *(const float4*)&X[(long)(kt + xrow) * NP + nb + xc4];
        Xs[xrow][xc4 + 0] = tf32r(xv.x); Xs[xrow][xc4 + 1] = tf32r(xv.y);
        Xs[xrow][xc4 + 2] = tf32r(xv.z); Xs[xrow][xc4 + 3] = tf32r(xv.w);
        __syncthreads();
#pragma unroll
        for (int kk = 0; kk < 16; kk += 8) {
            uint32_t a[2][4], b[4][2];
#pragma unroll
            for (int mo = 0; mo < 2; mo++) {
                int r0 = warp_o * 32 + mo * 16 + g;
                a[mo][0] = __float_as_uint(Ws[r0][kk + j]);
                a[mo][1] = __float_as_uint(Ws[r0 + 8][kk + j]);
                a[mo][2] = __float_as_uint(Ws[r0][kk + j + 4]);
                a[mo][3] = __float_as_uint(Ws[r0 + 8][kk + j + 4]);
            }
#pragma unroll
            for (int nn = 0; nn < 4; nn++) {
                int cc = warp_n * 32 + nn * 8 + g;
                b[nn][0] = __float_as_uint(Xs[kk + j][cc]);
                b[nn][1] = __float_as_uint(Xs[kk + j + 4][cc]);
            }
#pragma unroll
            for (int mo = 0; mo < 2; mo++)
#pragma unroll
                for (int nn = 0; nn < 4; nn++)
                    mma_tf32(acc[mo][nn], a[mo], b[nn]);
        }
        __syncthreads();
    }

#pragma unroll
    for (int mo = 0; mo < 2; mo++) {
        int r0 = warp_o * 32 + mo * 16 + g;
        float bs0 = bias ? bias[r0] : 0.f;
        float bs1 = bias ? bias[r0 + 8] : 0.f;
#pragma unroll
        for (int nn = 0; nn < 4; nn++) {
            int col = nb + warp_n * 32 + nn * 8 + j * 2;
            float2 v0 = make_float2(acc[mo][nn][0] + bs0, acc[mo][nn][1] + bs0);
            float2 v1 = make_float2(acc[mo][nn][2] + bs1, acc[mo][nn][3] + bs1);
            *(float2*)&Y[(long)r0 * NP + col] = v0;
            *(float2*)&Y[(long)(r0 + 8) * NP + col] = v1;
        }
    }
}

// shared X, two weight/output sets split along o. grid(49, Otot/128, Bb)
__global__ void gemm_dualW_k(const float* __restrict__ W1, const float* __restrict__ W2,
                             int osplit, const float* __restrict__ X, long xB,
                             float* __restrict__ Y1, float* __restrict__ Y2, long yB, int I)
{
    __shared__ float Ws[128][20];
    __shared__ float Xs[16][65];
    int ob = blockIdx.y * 128, b = blockIdx.z;
    const float* W; float* Y;
    if (ob < osplit) { W = W1 + (long)ob * I;            Y = Y1 + (long)b * yB + (long)ob * NP; }
    else             { W = W2 + (long)(ob - osplit) * I; Y = Y2 + (long)b * yB + (long)(ob - osplit) * NP; }
    gemm_core(W, X + (long)b * xB, Y, nullptr, I, blockIdx.x * 64, Ws, Xs);
}

// two full (W,X,Y,bias) jobs selected by grid.z>>1; batch = grid.z&1. grid(49, 2, 4)
__global__ void gemm_dualX_k(const float* __restrict__ W1, const float* __restrict__ W2,
                             const float* __restrict__ X1, const float* __restrict__ X2, long xB,
                             float* __restrict__ Y1, float* __restrict__ Y2, long yB,
                             const float* __restrict__ b1, const float* __restrict__ b2, int I)
{
    __shared__ float Ws[128][20];
    __shared__ float Xs[16][65];
    int z = blockIdx.z, b = z & 1, sel = z >> 1;
    int ob = blockIdx.y * 128;
    const float* W = (sel ? W2 : W1) + (long)ob * I;
    const float* X = (sel ? X2 : X1) + (long)b * xB;
    float*       Y = (sel ? Y2 : Y1) + (long)b * yB + (long)ob * NP;
    const float* bs = sel ? b2 : b1;
    gemm_core(W, X, Y, bs ? bs + ob : nullptr, I, blockIdx.x * 64, Ws, Xs);
}

// plain single gemm (gate). grid(49, O/128, Bb)
__global__ void gemm_tf32_k(const float* __restrict__ W, const float* __restrict__ X,
                            float* __restrict__ Y, const float* __restrict__ bias,
                            int I, long xB, long yB)
{
    __shared__ float Ws[128][20];
    __shared__ float Xs[16][65];
    int ob = blockIdx.y * 128, b = blockIdx.z;
    gemm_core(W + (long)ob * I, X + (long)b * xB, Y + (long)b * yB + (long)ob * NP,
              bias ? bias + ob : nullptr, I, blockIdx.x * 64, Ws, Xs);
}

// ---------------- fused DFT helpers ----------------
__device__ __forceinline__ void load_tables(float2* T1, float2* T2, float2* T3, int tid)
{
    for (int i = tid; i < HT; i += 256) {
        int n = i >> 5, k = i & 31;
        float c = 0.f, s = 0.f;
        if (k < 29) { int m = (n * k) % 56; sincospif(2.f * (float)m / 56.f, &s, &c); }
        T1[i] = make_float2(c, s);
    }
    for (int i = tid; i < NP; i += 256) {
        int r = i / 56, kh = i % 56;
        int m = (r * kh) % 56;
        float c, s; sincospif(2.f * (float)m / 56.f, &s, &c);
        T2[i] = make_float2(c, s);
    }
    for (int i = tid; i < 29 * 56; i += 256) {
        int k = i / 56, x = i % 56;
        int m = (k * x) % 56;
        float c, s; sincospif(2.f * (float)m / 56.f, &s, &c);
        float mult = (k == 0 || k == 28) ? 1.f : 2.f;
        T3[i] = make_float2(mult * c, -mult * s);
    }
}

__device__ __forceinline__ void r2cw_stage(const float* img, const float2* T1,
                                           float2* out, int tid)
{
    for (int o = tid; o < HT; o += 256) {
        int r = o >> 5, k = o & 31;
        if (k >= 29) continue;
        const float* xr = img + r * 56;
        float ac = 0.f, as = 0.f;
#pragma unroll 14
        for (int n = 0; n < 56; n++) {
            float2 w = T1[n * 32 + k];
            float v = xr[n];
            ac = fmaf(v, w.x, ac);
            as = fmaf(v, w.y, as);
        }
        out[o] = make_float2(ac, -as);
    }
}

template<int SG>
__device__ __forceinline__ void c2ch_stage(const float2* in, const float2* T2,
                                           float2* out, int tid)
{
    for (int o = tid; o < HT; o += 256) {
        int kh = o >> 5, kx = o & 31;
        if (kx >= 29) continue;
        float pr = 0.f, pi = 0.f;
#pragma unroll 14
        for (int r = 0; r < 56; r++) {
            float2 w = T2[r * 56 + kh];
            float2 v = in[r * 32 + kx];
            if (SG > 0) {
                pr = fmaf(v.x, w.x, fmaf(v.y, w.y, pr));
                pi = fmaf(v.y, w.x, fmaf(-v.x, w.y, pi));
            } else {
                pr = fmaf(v.x, w.x, fmaf(-v.y, w.y, pr));
                pi = fmaf(v.y, w.x, fmaf(v.x, w.y, pi));
            }
        }
        out[o] = make_float2(pr, pi);
    }
}

// ---------------- fused spectral branch ----------------
extern "C" __global__ void spec_fused_k(const float* __restrict__ sq,
                                        const float* __restrict__ skv,
                                        const float* __restrict__ dww,
                                        const float* __restrict__ dwb,
                                        float* __restrict__ out)
{
    extern __shared__ float sm[];
    float*  img = sm;
    float2* A   = (float2*)(sm + NP);
    float2* Bf  = A + HT;
    float2* Cf  = Bf + HT;
    float2* T1  = Cf + HT;
    float2* T2  = T1 + HT;
    float2* T3  = T2 + NP;
    int tid = threadIdx.x;
    int c = blockIdx.x, b = blockIdx.y;

    load_tables(T1, T2, T3, tid);
    const float* qp = sq  + ((long)b * 256 + c) * NP;
    const float* kp = skv + ((long)b * 512 + c) * NP;
    const float* vp = skv + ((long)b * 512 + 256 + c) * NP;

    for (int i = tid; i < NP; i += 256) img[i] = qp[i];
    __syncthreads();
    r2cw_stage(img, T1, A, tid);
    __syncthreads();
    c2ch_stage<1>(A, T2, Cf, tid);
    for (int i = tid; i < NP; i += 256) img[i] = kp[i];
    __syncthreads();
    r2cw_stage(img, T1, A, tid);
    __syncthreads();
    c2ch_stage<1>(A, T2, Bf, tid);
    __syncthreads();
    for (int o = tid; o < HT; o += 256) {
        if ((o & 31) >= 29) continue;
        float2 a = Cf[o], bb = Bf[o];
        A[o] = make_float2(a.x * bb.x - a.y * bb.y, a.x * bb.y + a.y * bb.x);
    }
    __syncthreads();
    c2ch_stage<-1>(A, T2, Bf, tid);
    for (int i = tid; i < NP; i += 256) img[i] = vp[i];
    __syncthreads();

    float wr[9];
#pragma unroll
    for (int i = 0; i < 9; i++) wr[i] = dww[c * 9 + i];
    float bsv = dwb[c];
    long ob = ((long)b * 256 + c) * NP;
    const float sc = 1.0f / 175616.0f;
    for (int o = tid; o < NP; o += 256) {
        int y = o / 56, x = o % 56;
        float acc = 0.f;
#pragma unroll
        for (int k = 0; k < 29; k++) {
            float2 w = T3[k * 56 + x];
            float2 v = Bf[y * 32 + k];
            acc = fmaf(v.x, w.x, fmaf(v.y, w.y, acc));
        }
        float dv = bsv;
#pragma unroll
        for (int dy = -1; dy <= 1; dy++) {
            int yy = y + dy;
            if ((unsigned)yy >= 56u) continue;
#pragma unroll
            for (int dx = -1; dx <= 1; dx++) {
                int xx = x + dx;
                if ((unsigned)xx >= 56u) continue;
                dv += wr[(dy + 1) * 3 + dx + 1] * img[yy * 56 + xx];
            }
        }
        out[ob + o] = (sc * acc) * img[o] + dv;
    }
}

// ---------------- fused token spectral-residual ----------------
extern "C" __global__ void token_fused_k(const float* __restrict__ tkv,
                                         const float* __restrict__ cw,
                                         float* __restrict__ xat)
{
    extern __shared__ float sm[];
    float*  img = sm;
    float2* A   = (float2*)(sm + NP);
    float2* Bf  = A + HT;
    float2* T1  = Bf + HT;
    float2* T2  = T1 + HT;
    float2* T3  = T2 + NP;
    int tid = threadIdx.x;
    int c = blockIdx.x, b = blockIdx.y;

    load_tables(T1, T2, T3, tid);
    const float* vp = tkv + (long)b * C2N + CN + (long)c * NP;
    for (int i = tid; i < NP; i += 256) img[i] = vp[i];
    __syncthreads();
    r2cw_stage(img, T1, A, tid);
    __syncthreads();
    c2ch_stage<1>(A, T2, Bf, tid);
    __syncthreads();
    for (int o = tid; o < HT; o += 256) {
        int kx = o & 31;
        if (kx >= 29) continue;
        int ky = o >> 5;
        long wb = (((long)c * 56 + ky) * 29 + kx) * 2;
        float wrr = cw[wb], wii = cw[wb + 1];
        float2 v = Bf[o];
        Bf[o] = make_float2(v.x * wrr - v.y * wii, v.x * wii + v.y * wrr);
    }
    __syncthreads();
    c2ch_stage<-1>(Bf, T2, A, tid);
    __syncthreads();
    long ob = ((long)b * 256 + c) * NP;
    const float sc = 1.0f / 3136.0f;
    for (int o = tid; o < NP; o += 256) {
        int y = o / 56, x = o % 56;
        float acc = 0.f;
#pragma unroll
        for (int k = 0; k < 29; k++) {
            float2 w = T3[k * 56 + x];
            float2 v = A[y * 32 + k];
            acc = fmaf(v.x, w.x, fmaf(v.y, w.y, acc));
        }
        xat[ob + o] += sc * acc;
    }
}

// ---------------- bf16 conversions (q+k merged) ----------------
__global__ void cvtqk2_k(const float* __restrict__ tq, const float* __restrict__ tkv,
                         __nv_bfloat162* __restrict__ qb, __nv_bfloat162* __restrict__ kb,
                         float scale)
{
    const long HALF = (long)Bb * 8 * NP * 16;
    long i = (long)blockIdx.x * blockDim.x + threadIdx.x;
    if (i >= 2 * HALF) return;
    int isK = i >= HALF;
    long ii = isK ? i - HALF : i;
    int p = (int)(ii & 15);
    long t = ii >> 4;
    int n = (int)(t % NP);
    long t2 = t / NP;
    int h = (int)(t2 & 7), b = (int)(t2 >> 3);
    if (isK) {
        long s0 = (long)b * C2N + (long)(h * 32 + 2 * p) * NP + n;
        kb[ii] = __floats2bfloat162_rn(tkv[s0], tkv[s0 + NP]);
    } else {
        long s0 = (long)b * CN + (long)(h * 32 + 2 * p) * NP + n;
        qb[ii] = __floats2bfloat162_rn(tq[s0] * scale, tq[s0 + NP] * scale);
    }
}

__global__ void cvtv_k(const float* __restrict__ tkv, __nv_bfloat162* __restrict__ dst)
{
    long i = (long)blockIdx.x * blockDim.x + threadIdx.x;
    if (i >= (long)Bb * 256 * NPH) return;
    int n2 = (int)(i % NPH);
    long cr = i / NPH;
    int b = (int)(cr >> 8), c = (int)(cr & 255);
    long s = (long)b * C2N + CN + (long)c * NP + 2 * n2;
    dst[i] = __floats2bfloat162_rn(tkv[s], tkv[s + 1]);
}

// ---------------- tensor-core flash attention (32-key smem tiles) ----------------
__device__ __forceinline__ void mma16816(float* c, const uint32_t* a, const uint32_t* b)
{
    asm volatile("mma.sync.aligned.m16n8k16.row.col.f32.bf16.bf16.f32 "
                 "{%0,%1,%2,%3}, {%4,%5,%6,%7}, {%8,%9}, {%0,%1,%2,%3};"
                 : "+f"(c[0]), "+f"(c[1]), "+f"(c[2]), "+f"(c[3])
                 : "r"(a[0]), "r"(a[1]), "r"(a[2]), "r"(a[3]), "r"(b[0]), "r"(b[1]));
}

__device__ __forceinline__ uint32_t packbf(float lo, float hi)
{
    __nv_bfloat162 h = __floats2bfloat162_rn(lo, hi);
    return *(uint32_t*)&h;
}

// grid(25, 8, Bb), block 256
__global__ void flash_mma_k(const __nv_bfloat162* __restrict__ Qb,
                            const __nv_bfloat162* __restrict__ Kb,
                            const __nv_bfloat162* __restrict__ Vb,
                            float* __restrict__ O)
{
    __shared__ uint32_t Ks[32 * 16];   // 32 keys x 16 bf162 (d=32)
    __shared__ uint32_t Vs[32 * 16];   // 32 d x 16 bf162 (32 keys)
    int b = blockIdx.z, h = blockIdx.y;
    int tid = threadIdx.x;
    int warp = tid >> 5, lane = tid & 31;
    int g = lane >> 2, j = lane & 3;
    int q0 = blockIdx.x * 128 + warp * 16;
    bool act = q0 < NP;
    int q0c = act ? q0 : NP - 16;
    const uint32_t* Qh = (const uint32_t*)(Qb + (long)(b * 8 + h) * NP * 16);
    const uint32_t* Kh = (const uint32_t*)(Kb + (long)(b * 8 + h) * NP * 16);
    const uint32_t* Vh = (const uint32_t*)(Vb + (long)(b * 256 + h * 32) * NPH);

    uint32_t qa[2][4];
#pragma unroll
    for (int kc = 0; kc < 2; kc++) {
        qa[kc][0] = Qh[(q0c + g)     * 16 + kc * 8 + j];
        qa[kc][1] = Qh[(q0c + g + 8) * 16 + kc * 8 + j];
        qa[kc][2] = Qh[(q0c + g)     * 16 + kc * 8 + j + 4];
        qa[kc][3] = Qh[(q0c + g + 8) * 16 + kc * 8 + j + 4];
    }

    float o_[4][4];
#pragma unroll
    for (int d = 0; d < 4; d++)
#pragma unroll
        for (int r = 0; r < 4; r++) o_[d][r] = 0.f;
    float mlo = -1e30f, mhi = -1e30f, llo = 0.f, lhi = 0.f;

#pragma unroll 1
    for (int kt = 0; kt < 98; kt++) {
        int kb = kt * 32;
        __syncthreads();
        {   // cooperative coalesced stage of 32-key K and V tiles
            int t0 = tid, t1 = tid + 256;
            Ks[t0] = Kh[kb * 16 + t0];
            Ks[t1] = Kh[kb * 16 + t1];
            Vs[t0] = Vh[(long)(t0 >> 4) * NPH + (kb >> 1) + (t0 & 15)];
            Vs[t1] = Vh[(long)(t1 >> 4) * NPH + (kb >> 1) + (t1 & 15)];
        }
        __syncthreads();

        float s[2][2][4];
#pragma unroll
        for (int sub = 0; sub < 2; sub++) {
#pragma unroll
            for (int nc = 0; nc < 2; nc++) {
                uint32_t kf[2][2];
#pragma unroll
                for (int kc = 0; kc < 2; kc++) {
                    int keyl = sub * 16 + nc * 8 + g;
                    kf[kc][0] = Ks[keyl * 16 + kc * 8 + j];
                    kf[kc][1] = Ks[keyl * 16 + kc * 8 + j + 4];
                }
                s[sub][nc][0] = 0.f; s[sub][nc][1] = 0.f;
                s[sub][nc][2] = 0.f; s[sub][nc][3] = 0.f;
                mma16816(s[sub][nc], qa[0], kf[0]);
                mma16816(s[sub][nc], qa[1], kf[1]);
            }
        }

        float tlo = -1e30f, thi = -1e30f;
#pragma unroll
        for (int sub = 0; sub < 2; sub++)
#pragma unroll
            for (int nc = 0; nc < 2; nc++) {
                tlo = fmaxf(tlo, fmaxf(s[sub][nc][0], s[sub][nc][1]));
                thi = fmaxf(thi, fmaxf(s[sub][nc][2], s[sub][nc][3]));
            }
        tlo = fmaxf(tlo, __shfl_xor_sync(0xffffffff, tlo, 1));
        tlo = fmaxf(tlo, __shfl_xor_sync(0xffffffff, tlo, 2));
        thi = fmaxf(thi, __shfl_xor_sync(0xffffffff, thi, 1));
        thi = fmaxf(thi, __shfl_xor_sync(0xffffffff, thi, 2));
        float mnlo = fmaxf(mlo, tlo), mnhi = fmaxf(mhi, thi);
        float clo = __expf(mlo - mnlo), chi = __expf(mhi - mnhi);

        uint32_t pa[2][4];
        float sumlo = 0.f, sumhi = 0.f;
#pragma unroll
        for (int sub = 0; sub < 2; sub++) {
#pragma unroll
            for (int nc = 0; nc < 2; nc++) {
                float p0 = __expf(s[sub][nc][0] - mnlo);
                float p1 = __expf(s[sub][nc][1] - mnlo);
                float p2 = __expf(s[sub][nc][2] - mnhi);
                float p3 = __expf(s[sub][nc][3] - mnhi);
                sumlo += p0 + p1; sumhi += p2 + p3;
                pa[sub][nc * 2 + 0] = packbf(p0, p1);
                pa[sub][nc * 2 + 1] = packbf(p2, p3);
            }
        }
        sumlo += __shfl_xor_sync(0xffffffff, sumlo, 1);
        sumlo += __shfl_xor_sync(0xffffffff, sumlo, 2);
        sumhi += __shfl_xor_sync(0xffffffff, sumhi, 1);
        sumhi += __shfl_xor_sync(0xffffffff, sumhi, 2);
        llo = llo * clo + sumlo;
        lhi = lhi * chi + sumhi;
#pragma unroll
        for (int d = 0; d < 4; d++) {
            o_[d][0] *= clo; o_[d][1] *= clo;
            o_[d][2] *= chi; o_[d][3] *= chi;
        }
        mlo = mnlo; mhi = mnhi;

#pragma unroll
        for (int dc = 0; dc < 4; dc++) {
#pragma unroll
            for (int sub = 0; sub < 2; sub++) {
                uint32_t vf[2];
                int vrow = (dc * 8 + g) * 16 + sub * 8;
                vf[0] = Vs[vrow + j];
                vf[1] = Vs[vrow + j + 4];
                mma16816(o_[dc], pa[sub], vf);
            }
        }
    }

    if (act) {
        float invlo = 1.f / llo, invhi = 1.f / lhi;
#pragma unroll
        for (int dc = 0; dc < 4; dc++) {
            long d0 = (long)(b * 256 + h * 32 + dc * 8 + 2 * j) * NP;
            O[d0 + q0 + g]          = o_[dc][0] * invlo;
            O[d0 + NP + q0 + g]     = o_[dc][1] * invlo;
            O[d0 + q0 + g + 8]      = o_[dc][2] * invhi;
            O[d0 + NP + q0 + g + 8] = o_[dc][3] * invhi;
        }
    }
}

// ---------------- fuse ----------------
__global__ void gate_k(const float* __restrict__ hraw, const float* __restrict__ gam,
                       const float* __restrict__ bet, const float* __restrict__ w2,
                       const float* __restrict__ b2p, float* __restrict__ gate)
{
    int b = blockIdx.y;
    int n = blockIdx.x * 128 + threadIdx.x;
    if (n >= NP) return;
    const float inv = rsqrtf(1.f + 1e-5f);
    const float* hb = hraw + (long)b * CN + n;
    float g = b2p[0];
#pragma unroll 8
    for (int c = 0; c < 256; c++) {
        float hv = hb[(long)c * NP] * inv * gam[c] + bet[c];
        g = fmaf(w2[c], fmaxf(hv, 0.f), g);
    }
    gate[(long)b * NP + n] = 1.f / (1.f + __expf(-g));
}

__global__ void blend_k(const float* __restrict__ fuse, const float* __restrict__ gate,
                        float* __restrict__ out)
{
    long i = (long)blockIdx.x * blockDim.x + threadIdx.x;
    if (i >= TOT) return;
    long b = i / CN;
    long n = i % NP;
    float g = gate[b * NP + n];
    long fidx = i + b * CN;
    out[i] = g * fuse[fidx] + (1.f - g) * fuse[fidx + CN];
}

extern "C" void kernel_launch(void* const* d_in, const int* in_sizes, int n_in,
                              void* d_out, int out_size)
{
    const float* x        = (const float*)d_in[0];
    const float* ctx      = (const float*)d_in[1];
    const float* s_q_w    = (const float*)d_in[2];
    const float* s_kv_w   = (const float*)d_in[3];
    const float* s_proj_w = (const float*)d_in[4];
    const float* s_proj_b = (const float*)d_in[5];
    const float* s_dw_w   = (const float*)d_in[6];
    const float* s_dw_b   = (const float*)d_in[7];
    const float* t_q_w    = (const float*)d_in[8];
    const float* t_kv_w   = (const float*)d_in[9];
    const float* t_proj_w = (const float*)d_in[10];
    const float* t_proj_b = (const float*)d_in[11];
    const float* t_cw     = (const float*)d_in[12];
    const float* g_w1     = (const float*)d_in[13];
    const float* g_bn_g   = (const float*)d_in[14];
    const float* g_bn_b   = (const float*)d_in[15];
    const float* g_w2     = (const float*)d_in[16];
    const float* g_b2     = (const float*)d_in[17];
    float* out = (float*)d_out;

    float *sq, *skv, *tq, *tkv, *spre, *xat, *fuse, *hbuf, *gate;
    __nv_bfloat162 *qb, *kb, *vb;
    cudaGetSymbolAddress((void**)&sq,   g_sq);
    cudaGetSymbolAddress((void**)&skv,  g_skv);
    cudaGetSymbolAddress((void**)&tq,   g_tq);
    cudaGetSymbolAddress((void**)&tkv,  g_tkv);
    cudaGetSymbolAddress((void**)&spre, g_spre);
    cudaGetSymbolAddress((void**)&xat,  g_xat);
    cudaGetSymbolAddress((void**)&fuse, g_fusb);
    cudaGetSymbolAddress((void**)&hbuf, g_hbuf);
    cudaGetSymbolAddress((void**)&gate, g_gate);
    cudaGetSymbolAddress((void**)&qb,   g_qb);
    cudaGetSymbolAddress((void**)&kb,   g_kb);
    cudaGetSymbolAddress((void**)&vb,   g_vb);

    const int SPEC_SMEM  = (NP + 2 * (3 * HT + HT + NP + 29 * 56)) * 4;
    const int TOKEN_SMEM = (NP + 2 * (2 * HT + HT + NP + 29 * 56)) * 4;
    cudaFuncSetAttribute(spec_fused_k,  cudaFuncAttributeMaxDynamicSharedMemorySize, SPEC_SMEM);
    cudaFuncSetAttribute(token_fused_k, cudaFuncAttributeMaxDynamicSharedMemorySize, TOKEN_SMEM);

    const float SCALE = 0.17677669529663687f;
    dim3 blk256(256), blk128(128);
    dim3 gC(256, Bb);

    // q GEMMs merged (O=512) and kv GEMMs merged (O=1024)
    gemm_dualW_k<<<dim3(49, 4, Bb), blk256>>>(s_q_w, t_q_w, 256, x, CN, sq, tq, CN, 256);
    gemm_dualW_k<<<dim3(49, 8, Bb), blk256>>>(s_kv_w, t_kv_w, 512, ctx, CN, skv, tkv, C2N, 256);

    spec_fused_k<<<gC, blk256, SPEC_SMEM>>>(sq, skv, s_dw_w, s_dw_b, spre);

    cvtqk2_k<<<dim3(6272), blk256>>>(tq, tkv, qb, kb, SCALE);
    cvtv_k<<<dim3(3136), blk256>>>(tkv, vb);
    flash_mma_k<<<dim3(25, 8, Bb), blk256>>>(qb, kb, vb, xat);
    token_fused_k<<<gC, blk256, TOKEN_SMEM>>>(tkv, t_cw, xat);

    // proj GEMMs merged via grid.z
    gemm_dualX_k<<<dim3(49, 2, 4), blk256>>>(s_proj_w, t_proj_w, spre, xat, CN,
                                             fuse, fuse + CN, C2N,
                                             s_proj_b, t_proj_b, 256);

    gemm_tf32_k<<<dim3(49, 2, Bb), blk256>>>(g_w1, fuse, hbuf, nullptr, 512, C2N, CN);
    gate_k<<<dim3(25, Bb), blk128>>>(hbuf, g_bn_g, g_bn_b, g_w2, g_b2, gate);
    blend_k<<<dim3((unsigned)((TOT + 255) / 256)), blk256>>>(fuse, gate, out);
}